// round 7
// baseline (speedup 1.0000x reference)
#include <cuda_runtime.h>
#include <cstdint>

// ---------------------------------------------------------------------------
// Problem constants
// ---------------------------------------------------------------------------
#define IN_DIM   1024
#define HID      2048
#define OUT_DIM  1000
#define BATCH    4096
#define STEPS    30
#define NPI      30
#define EPSN     1e-12f

#define G_IN  128
#define G_REC 256
#define G_OUT 64
#define NB_PI (G_IN + G_REC + G_OUT)

// ---------------------------------------------------------------------------
// Device scratch (allocation-free rule: __device__ globals)
// ---------------------------------------------------------------------------
__device__ float g_u[6144];
__device__ float g_y[6144];
__device__ float g_partY[3][256];
__device__ float g_partZ[3][256];
__device__ float g_sigpart[3][256];
__device__ float g_inv_sigma[3];

__device__ float g_xproj[(size_t)BATCH * HID];
__device__ float g_h0[(size_t)BATCH * HID];
__device__ float g_h1[(size_t)BATCH * HID];

// ---------------------------------------------------------------------------
// Power iteration (fp32, reference-exact sequence)
// ---------------------------------------------------------------------------
struct PiCtx { int m, bg, G, M, N; const float* W; float* ubuf; float* ybuf; };

__device__ __forceinline__ PiCtx pi_ctx(int b, const float* Win, const float* Wrec,
                                        const float* Wout) {
    PiCtx c;
    if (b < G_IN) {
        c.m = 0; c.bg = b; c.G = G_IN; c.M = HID; c.N = IN_DIM;
        c.W = Win; c.ubuf = g_u; c.ybuf = g_y;
    } else if (b < G_IN + G_REC) {
        c.m = 1; c.bg = b - G_IN; c.G = G_REC; c.M = HID; c.N = HID;
        c.W = Wrec; c.ubuf = g_u + 2048; c.ybuf = g_y + 2048;
    } else {
        c.m = 2; c.bg = b - G_IN - G_REC; c.G = G_OUT; c.M = OUT_DIM; c.N = HID;
        c.W = Wout; c.ubuf = g_u + 4096; c.ybuf = g_y + 4096;
    }
    return c;
}

// Parallel fixed-order sum of G partials (deterministic tree). red: >=256 floats.
__device__ __forceinline__ float block_sum_partials(const float* part, int G, float* red) {
    int t = threadIdx.x;
    red[t] = (t < G) ? part[t] : 0.0f;
    __syncthreads();
#pragma unroll
    for (int s = 128; s > 0; s >>= 1) {
        if (t < s) red[t] += red[t + s];
        __syncthreads();
    }
    float v = red[0];
    __syncthreads();
    return v;
}

__global__ void pi_init() {
    int t = threadIdx.x;
    for (int i = t; i < 2048; i += 256) {
        g_u[i] = 1.0f;
        g_u[2048 + i] = 1.0f;
        if (i < OUT_DIM) g_u[4096 + i] = 1.0f;
    }
    for (int g = t; g < 256; g += 256) {
        g_partZ[0][g] = 0.0f; g_partZ[1][g] = 0.0f; g_partZ[2][g] = 0.0f;
    }
    if (t == 0) {
        g_partZ[0][0] = (float)HID;
        g_partZ[1][0] = (float)HID;
        g_partZ[2][0] = (float)OUT_DIM;
    }
}

__global__ void pi_phaseY(const float* __restrict__ Win, const float* __restrict__ Wrec,
                          const float* __restrict__ Wout) {
    PiCtx c = pi_ctx(blockIdx.x, Win, Wrec, Wout);
    __shared__ float red[256];
    __shared__ float ssq[64];
    float ss = block_sum_partials(g_partZ[c.m], c.G, red);
    float su = 1.0f / (sqrtf(ss) + EPSN);

    int cpb = c.N / c.G;
    int tpc = 256 / cpb;
    int cl = threadIdx.x % cpb;
    int seg = threadIdx.x / cpb;
    int col = c.bg * cpb + cl;
    int rps = c.M / tpc;
    int r0 = seg * rps;

    const float* Wc = c.W + col;
    float a0 = 0.f, a1 = 0.f, a2 = 0.f, a3 = 0.f;
    int i = r0;
    for (; i + 3 < r0 + rps; i += 4) {
        a0 += Wc[(size_t)(i + 0) * c.N] * c.ubuf[i + 0];
        a1 += Wc[(size_t)(i + 1) * c.N] * c.ubuf[i + 1];
        a2 += Wc[(size_t)(i + 2) * c.N] * c.ubuf[i + 2];
        a3 += Wc[(size_t)(i + 3) * c.N] * c.ubuf[i + 3];
    }
    for (; i < r0 + rps; ++i) a0 += Wc[(size_t)i * c.N] * c.ubuf[i];
    float acc = (a0 + a1) + (a2 + a3);

    red[threadIdx.x] = acc;
    __syncthreads();
    if (seg == 0) {
        float tot = 0.0f;
        for (int s = 0; s < tpc; ++s) tot += red[cl + s * cpb];
        float yv = tot * su;
        c.ybuf[col] = yv;
        ssq[cl] = yv * yv;
    }
    __syncthreads();
    if (threadIdx.x == 0) {
        float p = 0.0f;
        for (int q = 0; q < cpb; ++q) p += ssq[q];
        g_partY[c.m][c.bg] = p;
    }
}

__global__ void pi_phaseZ(const float* __restrict__ Win, const float* __restrict__ Wrec,
                          const float* __restrict__ Wout) {
    PiCtx c = pi_ctx(blockIdx.x, Win, Wrec, Wout);
    __shared__ float red[256];
    float ss = block_sum_partials(g_partY[c.m], c.G, red);
    float sv = 1.0f / (sqrtf(ss) + EPSN);

    int warp = threadIdx.x >> 5, lane = threadIdx.x & 31;
    int rpb = (c.M + c.G - 1) / c.G;
    int rend = min(c.bg * rpb + rpb, c.M);

    float acc2 = 0.0f;
    for (int r = c.bg * rpb + warp; r < rend; r += 8) {
        const float* row = c.W + (size_t)r * c.N;
        float a0 = 0.f, a1 = 0.f, a2 = 0.f, a3 = 0.f;
        for (int j = lane; j < c.N; j += 128) {   // N in {1024,2048}: /128 exact
            a0 += row[j] * c.ybuf[j];
            a1 += row[j + 32] * c.ybuf[j + 32];
            a2 += row[j + 64] * c.ybuf[j + 64];
            a3 += row[j + 96] * c.ybuf[j + 96];
        }
        float a = (a0 + a1) + (a2 + a3);
        for (int o = 16; o; o >>= 1) a += __shfl_down_sync(0xffffffffu, a, o);
        if (lane == 0) {
            float z = a * sv;
            c.ubuf[r] = z;
            acc2 += z * z;
        }
    }
    __shared__ float wsq[8];
    if (lane == 0) wsq[warp] = acc2;
    __syncthreads();
    if (threadIdx.x == 0) {
        float p = 0.0f;
        for (int w = 0; w < 8; ++w) p += wsq[w];
        g_partZ[c.m][c.bg] = p;
    }
}

__global__ void pi_sigma(const float* __restrict__ Win, const float* __restrict__ Wrec,
                         const float* __restrict__ Wout) {
    PiCtx c = pi_ctx(blockIdx.x, Win, Wrec, Wout);
    __shared__ float red[256];
    float ssz = block_sum_partials(g_partZ[c.m], c.G, red);
    float ssy = block_sum_partials(g_partY[c.m], c.G, red);
    float su = 1.0f / (sqrtf(ssz) + EPSN);
    float sv = 1.0f / (sqrtf(ssy) + EPSN);

    int warp = threadIdx.x >> 5, lane = threadIdx.x & 31;
    int rpb = (c.M + c.G - 1) / c.G;
    int rend = min(c.bg * rpb + rpb, c.M);

    float contrib = 0.0f;
    for (int r = c.bg * rpb + warp; r < rend; r += 8) {
        const float* row = c.W + (size_t)r * c.N;
        float a0 = 0.f, a1 = 0.f, a2 = 0.f, a3 = 0.f;
        for (int j = lane; j < c.N; j += 128) {
            a0 += row[j] * c.ybuf[j];
            a1 += row[j + 32] * c.ybuf[j + 32];
            a2 += row[j + 64] * c.ybuf[j + 64];
            a3 += row[j + 96] * c.ybuf[j + 96];
        }
        float a = (a0 + a1) + (a2 + a3);
        for (int o = 16; o; o >>= 1) a += __shfl_down_sync(0xffffffffu, a, o);
        if (lane == 0) contrib += (su * c.ubuf[r]) * (sv * a);
    }
    __shared__ float wsq[8];
    if (lane == 0) wsq[warp] = contrib;
    __syncthreads();
    if (threadIdx.x == 0) {
        float p = 0.0f;
        for (int w = 0; w < 8; ++w) p += wsq[w];
        g_sigpart[c.m][c.bg] = p;
    }
}

__global__ void pi_finalize() {
    int m = threadIdx.x;
    if (m < 3) {
        int G = (m == 1) ? G_REC : ((m == 0) ? G_IN : G_OUT);
        float s = 0.0f;
        for (int g = 0; g < G; ++g) s += g_sigpart[m][g];
        g_inv_sigma[m] = 1.0f / s;
    }
}

// ---------------------------------------------------------------------------
// 3x-bf16 tensor-core GEMM (NT), mma.sync.m16n8k16.bf16, 2-stage smem pipeline.
//   C[m,n] = epi( (sum_k A[m,k]*B[n,k]) * inv_sigma + bias[n] [+ add] [tanh] )
// Split: hi = bf16(x), lo = bf16(x - hi); accumulate hh + hl + lh in fp32.
// Smem packs {hi pair, lo pair} per 8B; one LDS.64 feeds hi+lo fragments.
// Tile 128x128x32, 8 warps (2Mx4N), warp tile 64x32. One sync per k-tile.
// ---------------------------------------------------------------------------
#define BM 128
#define BN 128
#define BKT 32
#define PSTRIDE 20                      // uint2 per row (160B rows)
#define STAGE_U2 (BM * PSTRIDE)         // 2560 uint2 = 20 KB per operand
#define SMEM_GEMM (4 * STAGE_U2 * 8)    // 2 stages x (A+B) = 80 KB

__device__ __forceinline__ void split2(float x0, float x1, uint32_t& hi, uint32_t& lo) {
    uint32_t h;
    asm("cvt.rn.bf16x2.f32 %0, %1, %2;" : "=r"(h) : "f"(x1), "f"(x0));
    float h0 = __uint_as_float(h << 16);
    float h1 = __uint_as_float(h & 0xffff0000u);
    float r0 = x0 - h0, r1 = x1 - h1;
    uint32_t l;
    asm("cvt.rn.bf16x2.f32 %0, %1, %2;" : "=r"(l) : "f"(r1), "f"(r0));
    hi = h; lo = l;
}

__device__ __forceinline__ void mma16(float* c, uint32_t a0, uint32_t a1, uint32_t a2,
                                      uint32_t a3, uint32_t b0, uint32_t b1) {
    asm volatile(
        "mma.sync.aligned.m16n8k16.row.col.f32.bf16.bf16.f32 "
        "{%0,%1,%2,%3}, {%4,%5,%6,%7}, {%8,%9}, {%0,%1,%2,%3};"
        : "+f"(c[0]), "+f"(c[1]), "+f"(c[2]), "+f"(c[3])
        : "r"(a0), "r"(a1), "r"(a2), "r"(a3), "r"(b0), "r"(b1));
}

template <bool DO_TANH, bool HAS_ADD>
__global__ __launch_bounds__(256)
void gemm_bf16(const float* __restrict__ A, const float* __restrict__ B,
               const float* __restrict__ bias, const float* __restrict__ add,
               float* __restrict__ C, int M, int N, int K, int sidx) {
    extern __shared__ __align__(16) uint2 smem[];
    // stage layout: [As0 | Bs0 | As1 | Bs1]
    uint2* As[2] = { smem,                smem + 2 * STAGE_U2 };
    uint2* Bs[2] = { smem + STAGE_U2,     smem + 3 * STAGE_U2 };

    int tid = threadIdx.x;
    int bm = blockIdx.y * BM, bn = blockIdx.x * BN;

    int rowq[4], k4q[4];
    bool bok[4];
#pragma unroll
    for (int q = 0; q < 4; ++q) {
        int idx = tid + q * 256;
        rowq[q] = idx >> 3;
        k4q[q] = (idx & 7) * 4;
        bok[q] = (bn + rowq[q]) < N;
    }

    int warp = tid >> 5, lane = tid & 31;
    int wm = (warp & 1) * 64;
    int wn = (warp >> 1) * 32;
    int g = lane >> 2;
    int t = lane & 3;

    float acc[4][4][4];
#pragma unroll
    for (int i = 0; i < 4; ++i)
#pragma unroll
        for (int j = 0; j < 4; ++j)
#pragma unroll
            for (int q = 0; q < 4; ++q) acc[i][j][q] = 0.0f;

    // fill stage 0 from tile 0
    float4 pa[4], pb[4];
#pragma unroll
    for (int q = 0; q < 4; ++q) {
        pa[q] = *(const float4*)(A + (size_t)(bm + rowq[q]) * K + k4q[q]);
        pb[q] = bok[q] ? *(const float4*)(B + (size_t)(bn + rowq[q]) * K + k4q[q])
                       : make_float4(0.f, 0.f, 0.f, 0.f);
    }
#pragma unroll
    for (int q = 0; q < 4; ++q) {
        uint32_t h01, l01, h23, l23;
        split2(pa[q].x, pa[q].y, h01, l01);
        split2(pa[q].z, pa[q].w, h23, l23);
        *(uint4*)&As[0][rowq[q] * PSTRIDE + (k4q[q] >> 1)] = make_uint4(h01, l01, h23, l23);
        split2(pb[q].x, pb[q].y, h01, l01);
        split2(pb[q].z, pb[q].w, h23, l23);
        *(uint4*)&Bs[0][rowq[q] * PSTRIDE + (k4q[q] >> 1)] = make_uint4(h01, l01, h23, l23);
    }
    __syncthreads();

    int KT = K / BKT;
    for (int kt = 0; kt < KT; ++kt) {
        int cur = kt & 1, nxt = cur ^ 1;
        bool more = (kt + 1 < KT);

        // issue next tile's global loads; latency hidden by MMA block below
        if (more) {
            int off = (kt + 1) * BKT;
#pragma unroll
            for (int q = 0; q < 4; ++q) {
                pa[q] = *(const float4*)(A + (size_t)(bm + rowq[q]) * K + off + k4q[q]);
                if (bok[q]) pb[q] = *(const float4*)(B + (size_t)(bn + rowq[q]) * K + off + k4q[q]);
            }
        }

        // MMAs on current stage
        const uint2* Ac = As[cur];
        const uint2* Bc = Bs[cur];
#pragma unroll
        for (int kp = 0; kp < 16; kp += 8) {
            uint2 Af[4][4];
#pragma unroll
            for (int mf = 0; mf < 4; ++mf) {
                int rb = wm + mf * 16 + g;
                Af[mf][0] = Ac[rb * PSTRIDE + kp + t];
                Af[mf][1] = Ac[(rb + 8) * PSTRIDE + kp + t];
                Af[mf][2] = Ac[rb * PSTRIDE + kp + t + 4];
                Af[mf][3] = Ac[(rb + 8) * PSTRIDE + kp + t + 4];
            }
#pragma unroll
            for (int nf = 0; nf < 4; ++nf) {
                int cb = wn + nf * 8 + g;
                uint2 B0 = Bc[cb * PSTRIDE + kp + t];
                uint2 B1 = Bc[cb * PSTRIDE + kp + t + 4];
#pragma unroll
                for (int mf = 0; mf < 4; ++mf) {
                    mma16(acc[mf][nf], Af[mf][0].x, Af[mf][1].x, Af[mf][2].x, Af[mf][3].x,
                          B0.x, B1.x);
                    mma16(acc[mf][nf], Af[mf][0].x, Af[mf][1].x, Af[mf][2].x, Af[mf][3].x,
                          B0.y, B1.y);
                    mma16(acc[mf][nf], Af[mf][0].y, Af[mf][1].y, Af[mf][2].y, Af[mf][3].y,
                          B0.x, B1.x);
                }
            }
        }

        // split + store next stage, then single sync
        if (more) {
#pragma unroll
            for (int q = 0; q < 4; ++q) {
                uint32_t h01, l01, h23, l23;
                split2(pa[q].x, pa[q].y, h01, l01);
                split2(pa[q].z, pa[q].w, h23, l23);
                *(uint4*)&As[nxt][rowq[q] * PSTRIDE + (k4q[q] >> 1)] = make_uint4(h01, l01, h23, l23);
                split2(pb[q].x, pb[q].y, h01, l01);
                split2(pb[q].z, pb[q].w, h23, l23);
                *(uint4*)&Bs[nxt][rowq[q] * PSTRIDE + (k4q[q] >> 1)] = make_uint4(h01, l01, h23, l23);
            }
            __syncthreads();
        }
    }

    // ---- epilogue ----
    float scale = g_inv_sigma[sidx];
    bool full = (bn + BN <= N);
#pragma unroll
    for (int mf = 0; mf < 4; ++mf) {
        int r0 = bm + wm + mf * 16 + g;
#pragma unroll
        for (int nf = 0; nf < 4; ++nf) {
            int c0 = bn + wn + nf * 8 + 2 * t;
            float* a = acc[mf][nf];
#pragma unroll
            for (int half = 0; half < 2; ++half) {
                int rr = r0 + half * 8;
                size_t base = (size_t)rr * N + c0;
                float v0 = a[half * 2 + 0];
                float v1 = a[half * 2 + 1];
                if (full) {
                    v0 = v0 * scale + bias[c0];
                    v1 = v1 * scale + bias[c0 + 1];
                    if (HAS_ADD) {
                        float2 ad = *(const float2*)(add + base);
                        v0 += ad.x; v1 += ad.y;
                    }
                    if (DO_TANH) { v0 = tanhf(v0); v1 = tanhf(v1); }
                    float2 o; o.x = v0; o.y = v1;
                    *(float2*)(C + base) = o;
                } else {
                    if (c0 < N) {
                        float w = v0 * scale + bias[c0];
                        if (HAS_ADD) w += add[base];
                        if (DO_TANH) w = tanhf(w);
                        C[base] = w;
                    }
                    if (c0 + 1 < N) {
                        float w = v1 * scale + bias[c0 + 1];
                        if (HAS_ADD) w += add[base + 1];
                        if (DO_TANH) w = tanhf(w);
                        C[base + 1] = w;
                    }
                }
            }
        }
    }
}

// Step 1 (h0 = 0): h = tanh(x_proj + b_rec)
__global__ void step1_kernel(const float* __restrict__ xp, const float* __restrict__ brec,
                             float* __restrict__ h) {
    size_t i = ((size_t)blockIdx.x * blockDim.x + threadIdx.x) * 4;
    float4 v = *(const float4*)(xp + i);
    int col = (int)(i & (HID - 1));
    v.x = tanhf(v.x + brec[col + 0]);
    v.y = tanhf(v.y + brec[col + 1]);
    v.z = tanhf(v.z + brec[col + 2]);
    v.w = tanhf(v.w + brec[col + 3]);
    *(float4*)(h + i) = v;
}

// ---------------------------------------------------------------------------
// Launch
// ---------------------------------------------------------------------------
extern "C" void kernel_launch(void* const* d_in, const int* in_sizes, int n_in,
                              void* d_out, int out_size) {
    (void)in_sizes; (void)n_in; (void)out_size;
    const float* x    = (const float*)d_in[0];
    const float* Win  = (const float*)d_in[1];
    const float* bin  = (const float*)d_in[2];
    const float* Wrec = (const float*)d_in[3];
    const float* brec = (const float*)d_in[4];
    const float* Wout = (const float*)d_in[5];
    const float* bout = (const float*)d_in[6];
    float* out = (float*)d_out;

    float *xproj, *h0, *h1;
    cudaGetSymbolAddress((void**)&xproj, g_xproj);
    cudaGetSymbolAddress((void**)&h0, g_h0);
    cudaGetSymbolAddress((void**)&h1, g_h1);

    cudaFuncSetAttribute(gemm_bf16<false, false>,
                         cudaFuncAttributeMaxDynamicSharedMemorySize, SMEM_GEMM);
    cudaFuncSetAttribute(gemm_bf16<true, true>,
                         cudaFuncAttributeMaxDynamicSharedMemorySize, SMEM_GEMM);

    // --- spectral norms (power iteration, fp32, exact reference sequence) ---
    pi_init<<<1, 256>>>();
    for (int it = 0; it < NPI; ++it) {
        pi_phaseY<<<NB_PI, 256>>>(Win, Wrec, Wout);
        pi_phaseZ<<<NB_PI, 256>>>(Win, Wrec, Wout);
    }
    pi_phaseY<<<NB_PI, 256>>>(Win, Wrec, Wout);   // final v = norm(W^T u)
    pi_sigma<<<NB_PI, 256>>>(Win, Wrec, Wout);    // sigma = u . (W v)
    pi_finalize<<<1, 32>>>();

    // --- x_proj = x @ Win^T / s_in + b_in ---
    gemm_bf16<false, false><<<dim3(HID / BN, BATCH / BM), 256, SMEM_GEMM>>>(
        x, Win, bin, nullptr, xproj, BATCH, HID, IN_DIM, 0);

    // --- step 1: h = tanh(x_proj + b_rec) ---
    step1_kernel<<<(BATCH * HID) / (256 * 4), 256>>>(xproj, brec, h0);

    // --- steps 2..30: h = tanh(x_proj + h @ Wrec^T / s_rec + b_rec) ---
    float* hin = h0;
    float* hout = h1;
    for (int s = 1; s < STEPS; ++s) {
        gemm_bf16<true, true><<<dim3(HID / BN, BATCH / BM), 256, SMEM_GEMM>>>(
            hin, Wrec, brec, xproj, hout, BATCH, HID, HID, 1);
        float* t = hin; hin = hout; hout = t;
    }

    // --- out = h @ Wout^T / s_out + b_out ---
    gemm_bf16<false, false><<<dim3((OUT_DIM + BN - 1) / BN, BATCH / BM), 256, SMEM_GEMM>>>(
        hin, Wout, bout, nullptr, out, BATCH, OUT_DIM, HID, 2);
}

// round 8
// speedup vs baseline: 1.4536x; 1.4536x over previous
#include <cuda_runtime.h>
#include <cstdint>

// ---------------------------------------------------------------------------
// Problem constants
// ---------------------------------------------------------------------------
#define IN_DIM   1024
#define HID      2048
#define OUT_DIM  1000
#define NPAD_OUT 1024
#define BATCH    4096
#define STEPS    30
#define NPI      30
#define EPSN     1e-12f

#define G_IN  128
#define G_REC 256
#define G_OUT 64
#define NB_PI (G_IN + G_REC + G_OUT)

// ---------------------------------------------------------------------------
// Device scratch (allocation-free rule: __device__ globals)
// ---------------------------------------------------------------------------
__device__ float g_u[6144];
__device__ float g_y[6144];
__device__ float g_partY[3][256];
__device__ float g_partZ[3][256];
__device__ float g_sigpart[3][256];
__device__ float g_inv_sigma[3];

// packed hi/lo operands: uint2 per 2 elems ({bf16x2 hi pair, bf16x2 lo pair})
__device__ uint2 g_xp[(size_t)BATCH * IN_DIM / 2];
__device__ uint2 g_Winp[(size_t)HID * IN_DIM / 2];
__device__ uint2 g_Wrecp[(size_t)HID * HID / 2];
__device__ uint2 g_Woutp[(size_t)NPAD_OUT * HID / 2];   // rows >= OUT_DIM zeroed
__device__ float g_xraw[(size_t)BATCH * HID];           // unscaled x @ Win^T
__device__ uint2 g_hp0[(size_t)BATCH * HID / 2];
__device__ uint2 g_hp1[(size_t)BATCH * HID / 2];

// ---------------------------------------------------------------------------
// bf16 split helpers
// ---------------------------------------------------------------------------
__device__ __forceinline__ void split2(float x0, float x1, uint32_t& hi, uint32_t& lo) {
    uint32_t h;
    asm("cvt.rn.bf16x2.f32 %0, %1, %2;" : "=r"(h) : "f"(x1), "f"(x0));
    float h0 = __uint_as_float(h << 16);
    float h1 = __uint_as_float(h & 0xffff0000u);
    float r0 = x0 - h0, r1 = x1 - h1;
    uint32_t l;
    asm("cvt.rn.bf16x2.f32 %0, %1, %2;" : "=r"(l) : "f"(r1), "f"(r0));
    hi = h; lo = l;
}

// ---------------------------------------------------------------------------
// Prepack: fp32 row-major -> packed uint2 pairs (4 elems / thread)
// ---------------------------------------------------------------------------
__global__ void prepack(const float* __restrict__ src, uint2* __restrict__ dst, int n4) {
    int i = blockIdx.x * 256 + threadIdx.x;
    if (i < n4) {
        float4 v = ((const float4*)src)[i];
        uint32_t h01, l01, h23, l23;
        split2(v.x, v.y, h01, l01);
        split2(v.z, v.w, h23, l23);
        ((uint4*)dst)[i] = make_uint4(h01, l01, h23, l23);
    }
}

// Same, but rows >= src_rows are zero (Wout padded to 1024 rows)
__global__ void prepack_pad(const float* __restrict__ src, uint2* __restrict__ dst,
                            int src_rows, int K4, int n4) {
    int i = blockIdx.x * 256 + threadIdx.x;
    if (i < n4) {
        int row = i / K4;
        uint4 o = make_uint4(0u, 0u, 0u, 0u);
        if (row < src_rows) {
            float4 v = ((const float4*)src)[i];
            uint32_t h01, l01, h23, l23;
            split2(v.x, v.y, h01, l01);
            split2(v.z, v.w, h23, l23);
            o = make_uint4(h01, l01, h23, l23);
        }
        ((uint4*)dst)[i] = o;
    }
}

// ---------------------------------------------------------------------------
// Power iteration (fp32, reference-exact sequence)
// ---------------------------------------------------------------------------
struct PiCtx { int m, bg, G, M, N; const float* W; float* ubuf; float* ybuf; };

__device__ __forceinline__ PiCtx pi_ctx(int b, const float* Win, const float* Wrec,
                                        const float* Wout) {
    PiCtx c;
    if (b < G_IN) {
        c.m = 0; c.bg = b; c.G = G_IN; c.M = HID; c.N = IN_DIM;
        c.W = Win; c.ubuf = g_u; c.ybuf = g_y;
    } else if (b < G_IN + G_REC) {
        c.m = 1; c.bg = b - G_IN; c.G = G_REC; c.M = HID; c.N = HID;
        c.W = Wrec; c.ubuf = g_u + 2048; c.ybuf = g_y + 2048;
    } else {
        c.m = 2; c.bg = b - G_IN - G_REC; c.G = G_OUT; c.M = OUT_DIM; c.N = HID;
        c.W = Wout; c.ubuf = g_u + 4096; c.ybuf = g_y + 4096;
    }
    return c;
}

__device__ __forceinline__ float block_sum_partials(const float* part, int G, float* red) {
    int t = threadIdx.x;
    red[t] = (t < G) ? part[t] : 0.0f;
    __syncthreads();
#pragma unroll
    for (int s = 128; s > 0; s >>= 1) {
        if (t < s) red[t] += red[t + s];
        __syncthreads();
    }
    float v = red[0];
    __syncthreads();
    return v;
}

__global__ void pi_init() {
    int t = threadIdx.x;
    for (int i = t; i < 2048; i += 256) {
        g_u[i] = 1.0f;
        g_u[2048 + i] = 1.0f;
        if (i < OUT_DIM) g_u[4096 + i] = 1.0f;
    }
    for (int g = t; g < 256; g += 256) {
        g_partZ[0][g] = 0.0f; g_partZ[1][g] = 0.0f; g_partZ[2][g] = 0.0f;
    }
    if (t == 0) {
        g_partZ[0][0] = (float)HID;
        g_partZ[1][0] = (float)HID;
        g_partZ[2][0] = (float)OUT_DIM;
    }
}

__global__ void pi_phaseY(const float* __restrict__ Win, const float* __restrict__ Wrec,
                          const float* __restrict__ Wout) {
    PiCtx c = pi_ctx(blockIdx.x, Win, Wrec, Wout);
    __shared__ float red[256];
    __shared__ float ssq[64];
    float ss = block_sum_partials(g_partZ[c.m], c.G, red);
    float su = 1.0f / (sqrtf(ss) + EPSN);

    int cpb = c.N / c.G;
    int tpc = 256 / cpb;
    int cl = threadIdx.x % cpb;
    int seg = threadIdx.x / cpb;
    int col = c.bg * cpb + cl;
    int rps = c.M / tpc;
    int r0 = seg * rps;

    const float* Wc = c.W + col;
    float a0 = 0.f, a1 = 0.f, a2 = 0.f, a3 = 0.f;
    int i = r0;
    for (; i + 3 < r0 + rps; i += 4) {
        a0 += Wc[(size_t)(i + 0) * c.N] * c.ubuf[i + 0];
        a1 += Wc[(size_t)(i + 1) * c.N] * c.ubuf[i + 1];
        a2 += Wc[(size_t)(i + 2) * c.N] * c.ubuf[i + 2];
        a3 += Wc[(size_t)(i + 3) * c.N] * c.ubuf[i + 3];
    }
    for (; i < r0 + rps; ++i) a0 += Wc[(size_t)i * c.N] * c.ubuf[i];
    float acc = (a0 + a1) + (a2 + a3);

    red[threadIdx.x] = acc;
    __syncthreads();
    if (seg == 0) {
        float tot = 0.0f;
        for (int s = 0; s < tpc; ++s) tot += red[cl + s * cpb];
        float yv = tot * su;
        c.ybuf[col] = yv;
        ssq[cl] = yv * yv;
    }
    __syncthreads();
    if (threadIdx.x == 0) {
        float p = 0.0f;
        for (int q = 0; q < cpb; ++q) p += ssq[q];
        g_partY[c.m][c.bg] = p;
    }
}

__global__ void pi_phaseZ(const float* __restrict__ Win, const float* __restrict__ Wrec,
                          const float* __restrict__ Wout) {
    PiCtx c = pi_ctx(blockIdx.x, Win, Wrec, Wout);
    __shared__ float red[256];
    float ss = block_sum_partials(g_partY[c.m], c.G, red);
    float sv = 1.0f / (sqrtf(ss) + EPSN);

    int warp = threadIdx.x >> 5, lane = threadIdx.x & 31;
    int rpb = (c.M + c.G - 1) / c.G;
    int rend = min(c.bg * rpb + rpb, c.M);

    float acc2 = 0.0f;
    for (int r = c.bg * rpb + warp; r < rend; r += 8) {
        const float* row = c.W + (size_t)r * c.N;
        float a0 = 0.f, a1 = 0.f, a2 = 0.f, a3 = 0.f;
        for (int j = lane; j < c.N; j += 128) {
            a0 += row[j] * c.ybuf[j];
            a1 += row[j + 32] * c.ybuf[j + 32];
            a2 += row[j + 64] * c.ybuf[j + 64];
            a3 += row[j + 96] * c.ybuf[j + 96];
        }
        float a = (a0 + a1) + (a2 + a3);
        for (int o = 16; o; o >>= 1) a += __shfl_down_sync(0xffffffffu, a, o);
        if (lane == 0) {
            float z = a * sv;
            c.ubuf[r] = z;
            acc2 += z * z;
        }
    }
    __shared__ float wsq[8];
    if (lane == 0) wsq[warp] = acc2;
    __syncthreads();
    if (threadIdx.x == 0) {
        float p = 0.0f;
        for (int w = 0; w < 8; ++w) p += wsq[w];
        g_partZ[c.m][c.bg] = p;
    }
}

__global__ void pi_sigma(const float* __restrict__ Win, const float* __restrict__ Wrec,
                         const float* __restrict__ Wout) {
    PiCtx c = pi_ctx(blockIdx.x, Win, Wrec, Wout);
    __shared__ float red[256];
    float ssz = block_sum_partials(g_partZ[c.m], c.G, red);
    float ssy = block_sum_partials(g_partY[c.m], c.G, red);
    float su = 1.0f / (sqrtf(ssz) + EPSN);
    float sv = 1.0f / (sqrtf(ssy) + EPSN);

    int warp = threadIdx.x >> 5, lane = threadIdx.x & 31;
    int rpb = (c.M + c.G - 1) / c.G;
    int rend = min(c.bg * rpb + rpb, c.M);

    float contrib = 0.0f;
    for (int r = c.bg * rpb + warp; r < rend; r += 8) {
        const float* row = c.W + (size_t)r * c.N;
        float a0 = 0.f, a1 = 0.f, a2 = 0.f, a3 = 0.f;
        for (int j = lane; j < c.N; j += 128) {
            a0 += row[j] * c.ybuf[j];
            a1 += row[j + 32] * c.ybuf[j + 32];
            a2 += row[j + 64] * c.ybuf[j + 64];
            a3 += row[j + 96] * c.ybuf[j + 96];
        }
        float a = (a0 + a1) + (a2 + a3);
        for (int o = 16; o; o >>= 1) a += __shfl_down_sync(0xffffffffu, a, o);
        if (lane == 0) contrib += (su * c.ubuf[r]) * (sv * a);
    }
    __shared__ float wsq[8];
    if (lane == 0) wsq[warp] = contrib;
    __syncthreads();
    if (threadIdx.x == 0) {
        float p = 0.0f;
        for (int w = 0; w < 8; ++w) p += wsq[w];
        g_sigpart[c.m][c.bg] = p;
    }
}

__global__ void pi_finalize() {
    int m = threadIdx.x;
    if (m < 3) {
        int G = (m == 1) ? G_REC : ((m == 0) ? G_IN : G_OUT);
        float s = 0.0f;
        for (int g = 0; g < G; ++g) s += g_sigpart[m][g];
        g_inv_sigma[m] = 1.0f / s;
    }
}

// ---------------------------------------------------------------------------
// 3x-bf16 mma.sync GEMM on PRE-PACKED operands (R6 loop structure).
// A: [M,K] packed, B: [Npad,K] packed. Mainloop fill = pure LDG128/STS128.
// OKIND 0: C=fp32 raw accum (xproj).  OKIND 1: rec step -> packed h with
// tanh(acc*s_rec + b_rec + raw*s_in + b_in).  OKIND 2: out, fp32, col-guarded.
// ---------------------------------------------------------------------------
#define BM 128
#define BN 128
#define BKT 32
#define PSTRIDE 20   // uint2 per row (160B: conflict-free)

__device__ __forceinline__ void mma16(float* c, uint32_t a0, uint32_t a1, uint32_t a2,
                                      uint32_t a3, uint32_t b0, uint32_t b1) {
    asm volatile(
        "mma.sync.aligned.m16n8k16.row.col.f32.bf16.bf16.f32 "
        "{%0,%1,%2,%3}, {%4,%5,%6,%7}, {%8,%9}, {%0,%1,%2,%3};"
        : "+f"(c[0]), "+f"(c[1]), "+f"(c[2]), "+f"(c[3])
        : "r"(a0), "r"(a1), "r"(a2), "r"(a3), "r"(b0), "r"(b1));
}

template <int OKIND>
__global__ __launch_bounds__(256)
void gemm_pk(const uint2* __restrict__ A, const uint2* __restrict__ B,
             const float* __restrict__ bias, const float* __restrict__ bias2,
             const float* __restrict__ raw, float* __restrict__ Cf,
             uint2* __restrict__ Cp, int M, int N, int Nreal, int K) {
    __shared__ __align__(16) uint2 As[BM * PSTRIDE];
    __shared__ __align__(16) uint2 Bs[BN * PSTRIDE];

    int tid = threadIdx.x;
    int bm = blockIdx.y * BM, bn = blockIdx.x * BN;
    int Kp = K >> 1;   // uint2 per row

    // fill mapping: idx -> row (128), u = uint4-within-row (8); 4 quanta
    int rowq[4], uq[4];
#pragma unroll
    for (int q = 0; q < 4; ++q) {
        int idx = tid + q * 256;
        rowq[q] = idx >> 3;
        uq[q] = (idx & 7) * 2;   // uint2 offset within row
    }

    int warp = tid >> 5, lane = tid & 31;
    int wm = (warp & 1) * 64;
    int wn = (warp >> 1) * 32;
    int g = lane >> 2;
    int t = lane & 3;

    float acc[4][4][4];
#pragma unroll
    for (int i = 0; i < 4; ++i)
#pragma unroll
        for (int j = 0; j < 4; ++j)
#pragma unroll
            for (int q = 0; q < 4; ++q) acc[i][j][q] = 0.0f;

    // prefetch tile 0 (pure loads)
    uint4 pa[4], pb[4];
#pragma unroll
    for (int q = 0; q < 4; ++q) {
        pa[q] = *(const uint4*)(A + (size_t)(bm + rowq[q]) * Kp + uq[q]);
        pb[q] = *(const uint4*)(B + (size_t)(bn + rowq[q]) * Kp + uq[q]);
    }

    int KT = K / BKT;
    for (int kt = 0; kt < KT; ++kt) {
        __syncthreads();   // previous tile fully consumed
#pragma unroll
        for (int q = 0; q < 4; ++q) {
            *(uint4*)&As[rowq[q] * PSTRIDE + uq[q]] = pa[q];
            *(uint4*)&Bs[rowq[q] * PSTRIDE + uq[q]] = pb[q];
        }
        __syncthreads();

        // issue next tile's loads; latency hidden by MMAs below
        if (kt + 1 < KT) {
            int off = (kt + 1) * 16;   // 16 uint2 per k-tile row
#pragma unroll
            for (int q = 0; q < 4; ++q) {
                pa[q] = *(const uint4*)(A + (size_t)(bm + rowq[q]) * Kp + off + uq[q]);
                pb[q] = *(const uint4*)(B + (size_t)(bn + rowq[q]) * Kp + off + uq[q]);
            }
        }

#pragma unroll
        for (int kp = 0; kp < 16; kp += 8) {
            uint2 Af[4][4];
#pragma unroll
            for (int mf = 0; mf < 4; ++mf) {
                int rb = wm + mf * 16 + g;
                Af[mf][0] = As[rb * PSTRIDE + kp + t];
                Af[mf][1] = As[(rb + 8) * PSTRIDE + kp + t];
                Af[mf][2] = As[rb * PSTRIDE + kp + t + 4];
                Af[mf][3] = As[(rb + 8) * PSTRIDE + kp + t + 4];
            }
#pragma unroll
            for (int nf = 0; nf < 4; ++nf) {
                int cb = wn + nf * 8 + g;
                uint2 B0 = Bs[cb * PSTRIDE + kp + t];
                uint2 B1 = Bs[cb * PSTRIDE + kp + t + 4];
#pragma unroll
                for (int mf = 0; mf < 4; ++mf) {
                    mma16(acc[mf][nf], Af[mf][0].x, Af[mf][1].x, Af[mf][2].x, Af[mf][3].x,
                          B0.x, B1.x);   // hi*hi
                    mma16(acc[mf][nf], Af[mf][0].x, Af[mf][1].x, Af[mf][2].x, Af[mf][3].x,
                          B0.y, B1.y);   // hi*lo
                    mma16(acc[mf][nf], Af[mf][0].y, Af[mf][1].y, Af[mf][2].y, Af[mf][3].y,
                          B0.x, B1.x);   // lo*hi
                }
            }
        }
    }

    // ---- epilogue ----
    float s_main = (OKIND == 1) ? g_inv_sigma[1] : ((OKIND == 2) ? g_inv_sigma[2] : 1.0f);
    float s_in = (OKIND == 1) ? g_inv_sigma[0] : 0.0f;
#pragma unroll
    for (int mf = 0; mf < 4; ++mf) {
        int r0 = bm + wm + mf * 16 + g;
#pragma unroll
        for (int nf = 0; nf < 4; ++nf) {
            int c0 = bn + wn + nf * 8 + 2 * t;
            float* a = acc[mf][nf];
#pragma unroll
            for (int half = 0; half < 2; ++half) {
                int rr = r0 + half * 8;
                float v0 = a[half * 2 + 0];
                float v1 = a[half * 2 + 1];
                if (OKIND == 0) {
                    size_t base = (size_t)rr * N + c0;
                    float2 o; o.x = v0; o.y = v1;
                    *(float2*)(Cf + base) = o;
                } else if (OKIND == 1) {
                    size_t base = (size_t)rr * N + c0;
                    float2 rw = *(const float2*)(raw + base);
                    v0 = tanhf(v0 * s_main + bias[c0] + rw.x * s_in + bias2[c0]);
                    v1 = tanhf(v1 * s_main + bias[c0 + 1] + rw.y * s_in + bias2[c0 + 1]);
                    uint32_t hi, lo;
                    split2(v0, v1, hi, lo);
                    Cp[((size_t)rr * N + c0) >> 1] = make_uint2(hi, lo);
                } else {
                    size_t base = (size_t)rr * Nreal;
                    if (c0 < Nreal)     Cf[base + c0]     = v0 * s_main + bias[c0];
                    if (c0 + 1 < Nreal) Cf[base + c0 + 1] = v1 * s_main + bias[c0 + 1];
                }
            }
        }
    }
}

// Step 1 (h0 = 0): h_packed = split( tanh(raw*s_in + b_in + b_rec) )
__global__ void step1_kernel(const float* __restrict__ xpraw, const float* __restrict__ bin,
                             const float* __restrict__ brec, uint2* __restrict__ hp) {
    size_t i = ((size_t)blockIdx.x * blockDim.x + threadIdx.x) * 4;
    float s_in = g_inv_sigma[0];
    float4 v = *(const float4*)(xpraw + i);
    int col = (int)(i & (HID - 1));
    v.x = tanhf(v.x * s_in + bin[col + 0] + brec[col + 0]);
    v.y = tanhf(v.y * s_in + bin[col + 1] + brec[col + 1]);
    v.z = tanhf(v.z * s_in + bin[col + 2] + brec[col + 2]);
    v.w = tanhf(v.w * s_in + bin[col + 3] + brec[col + 3]);
    uint32_t h01, l01, h23, l23;
    split2(v.x, v.y, h01, l01);
    split2(v.z, v.w, h23, l23);
    *(uint4*)(hp + (i >> 1)) = make_uint4(h01, l01, h23, l23);
}

// ---------------------------------------------------------------------------
// Launch. Order puts the xproj GEMM at launch slot 6 so ncu (-s 5 -c 1)
// profiles the GEMM instead of a PI matvec.
// ---------------------------------------------------------------------------
extern "C" void kernel_launch(void* const* d_in, const int* in_sizes, int n_in,
                              void* d_out, int out_size) {
    (void)in_sizes; (void)n_in; (void)out_size;
    const float* x    = (const float*)d_in[0];
    const float* Win  = (const float*)d_in[1];
    const float* bin  = (const float*)d_in[2];
    const float* Wrec = (const float*)d_in[3];
    const float* brec = (const float*)d_in[4];
    const float* Wout = (const float*)d_in[5];
    const float* bout = (const float*)d_in[6];
    float* out = (float*)d_out;

    uint2 *xp, *winp, *wrecp, *woutp, *hp0, *hp1;
    float* xraw;
    cudaGetSymbolAddress((void**)&xp, g_xp);
    cudaGetSymbolAddress((void**)&winp, g_Winp);
    cudaGetSymbolAddress((void**)&wrecp, g_Wrecp);
    cudaGetSymbolAddress((void**)&woutp, g_Woutp);
    cudaGetSymbolAddress((void**)&xraw, g_xraw);
    cudaGetSymbolAddress((void**)&hp0, g_hp0);
    cudaGetSymbolAddress((void**)&hp1, g_hp1);

    // 1: init
    pi_init<<<1, 256>>>();
    // 2-5: prepack all static operands
    prepack<<<(BATCH * IN_DIM / 4) / 256, 256>>>(x, xp, BATCH * IN_DIM / 4);
    prepack<<<(HID * IN_DIM / 4) / 256, 256>>>(Win, winp, HID * IN_DIM / 4);
    prepack<<<(HID * HID / 4) / 256, 256>>>(Wrec, wrecp, HID * HID / 4);
    prepack_pad<<<(NPAD_OUT * HID / 4) / 256, 256>>>(Wout, woutp, OUT_DIM, HID / 4,
                                                     NPAD_OUT * HID / 4);
    // 6: raw xproj GEMM (sigma-independent) — the ncu-profiled launch
    gemm_pk<0><<<dim3(HID / BN, BATCH / BM), 256>>>(
        xp, winp, nullptr, nullptr, nullptr, xraw, nullptr, BATCH, HID, HID, IN_DIM);

    // --- spectral norms (power iteration, fp32, exact reference sequence) ---
    for (int it = 0; it < NPI; ++it) {
        pi_phaseY<<<NB_PI, 256>>>(Win, Wrec, Wout);
        pi_phaseZ<<<NB_PI, 256>>>(Win, Wrec, Wout);
    }
    pi_phaseY<<<NB_PI, 256>>>(Win, Wrec, Wout);   // final v = norm(W^T u)
    pi_sigma<<<NB_PI, 256>>>(Win, Wrec, Wout);    // sigma = u . (W v)
    pi_finalize<<<1, 32>>>();

    // step 1: h = tanh(xraw*s_in + b_in + b_rec), packed
    step1_kernel<<<(BATCH * HID) / (256 * 4), 256>>>(xraw, bin, brec, hp0);

    // steps 2..30: h' = tanh(h@Wrec^T*s_rec + b_rec + xraw*s_in + b_in), packed
    uint2* hin = hp0;
    uint2* hout = hp1;
    for (int s = 1; s < STEPS; ++s) {
        gemm_pk<1><<<dim3(HID / BN, BATCH / BM), 256>>>(
            hin, wrecp, brec, bin, xraw, nullptr, hout, BATCH, HID, HID, HID);
        uint2* tmp = hin; hin = hout; hout = tmp;
    }

    // out = h @ Wout^T * s_out + b_out (B padded to 1024 rows; stores guarded)
    gemm_pk<2><<<dim3(NPAD_OUT / BN, BATCH / BM), 256>>>(
        hin, woutp, bout, nullptr, nullptr, out, nullptr, BATCH, NPAD_OUT, OUT_DIM, HID);
}

// round 9
// speedup vs baseline: 1.5044x; 1.0349x over previous
#include <cuda_runtime.h>
#include <cstdint>

// ---------------------------------------------------------------------------
// Problem constants
// ---------------------------------------------------------------------------
#define IN_DIM   1024
#define HID      2048
#define OUT_DIM  1000
#define NPAD_OUT 1024
#define BATCH    4096
#define STEPS    30
#define NPI      30
#define EPSN     1e-12f

// phaseZ / sigma block groups (row-split)
#define GZ_IN  128
#define GZ_REC 256
#define GZ_OUT 64
#define NBZ (GZ_IN + GZ_REC + GZ_OUT)    // 448
// phaseY block groups (col-split, 32 cols/block for full coalescing)
#define GY_IN  32     // 1024/32
#define GY_REC 64     // 2048/32
#define GY_OUT 64     // N=2048 cols
#define NBY (GY_IN + GY_REC + GY_OUT)    // 160

// ---------------------------------------------------------------------------
// Device scratch (allocation-free rule: __device__ globals)
// ---------------------------------------------------------------------------
__device__ float g_u[6144];
__device__ float g_y[6144];
__device__ float g_partY[3][64];    // phaseY partials (G_Y <= 64)
__device__ float g_partZ[3][256];   // phaseZ partials (G_Z <= 256)
__device__ float g_sigpart[3][256];
__device__ float g_inv_sigma[3];

// packed hi/lo operands: uint2 per 2 elems ({bf16x2 hi pair, bf16x2 lo pair})
__device__ uint2 g_xp[(size_t)BATCH * IN_DIM / 2];
__device__ uint2 g_Winp[(size_t)HID * IN_DIM / 2];
__device__ uint2 g_Wrecp[(size_t)HID * HID / 2];
__device__ uint2 g_Woutp[(size_t)NPAD_OUT * HID / 2];
__device__ float g_xraw[(size_t)BATCH * HID];
__device__ uint2 g_hp0[(size_t)BATCH * HID / 2];
__device__ uint2 g_hp1[(size_t)BATCH * HID / 2];

// ---------------------------------------------------------------------------
// bf16 split helpers
// ---------------------------------------------------------------------------
__device__ __forceinline__ void split2(float x0, float x1, uint32_t& hi, uint32_t& lo) {
    uint32_t h;
    asm("cvt.rn.bf16x2.f32 %0, %1, %2;" : "=r"(h) : "f"(x1), "f"(x0));
    float h0 = __uint_as_float(h << 16);
    float h1 = __uint_as_float(h & 0xffff0000u);
    float r0 = x0 - h0, r1 = x1 - h1;
    uint32_t l;
    asm("cvt.rn.bf16x2.f32 %0, %1, %2;" : "=r"(l) : "f"(r1), "f"(r0));
    hi = h; lo = l;
}

// ---------------------------------------------------------------------------
// Prepack
// ---------------------------------------------------------------------------
__global__ void prepack(const float* __restrict__ src, uint2* __restrict__ dst, int n4) {
    int i = blockIdx.x * 256 + threadIdx.x;
    if (i < n4) {
        float4 v = ((const float4*)src)[i];
        uint32_t h01, l01, h23, l23;
        split2(v.x, v.y, h01, l01);
        split2(v.z, v.w, h23, l23);
        ((uint4*)dst)[i] = make_uint4(h01, l01, h23, l23);
    }
}

__global__ void prepack_pad(const float* __restrict__ src, uint2* __restrict__ dst,
                            int src_rows, int K4, int n4) {
    int i = blockIdx.x * 256 + threadIdx.x;
    if (i < n4) {
        int row = i / K4;
        uint4 o = make_uint4(0u, 0u, 0u, 0u);
        if (row < src_rows) {
            float4 v = ((const float4*)src)[i];
            uint32_t h01, l01, h23, l23;
            split2(v.x, v.y, h01, l01);
            split2(v.z, v.w, h23, l23);
            o = make_uint4(h01, l01, h23, l23);
        }
        ((uint4*)dst)[i] = o;
    }
}

// ---------------------------------------------------------------------------
// Power iteration (fp32, reference-exact sequence)
// ---------------------------------------------------------------------------
struct PiCtx { int m, bg, G, M, N; const float* W; float* ubuf; float* ybuf; };

// Z-layout context (row split): used by phaseZ and sigma
__device__ __forceinline__ PiCtx pi_ctxZ(int b, const float* Win, const float* Wrec,
                                         const float* Wout) {
    PiCtx c;
    if (b < GZ_IN) {
        c.m = 0; c.bg = b; c.G = GZ_IN; c.M = HID; c.N = IN_DIM;
        c.W = Win; c.ubuf = g_u; c.ybuf = g_y;
    } else if (b < GZ_IN + GZ_REC) {
        c.m = 1; c.bg = b - GZ_IN; c.G = GZ_REC; c.M = HID; c.N = HID;
        c.W = Wrec; c.ubuf = g_u + 2048; c.ybuf = g_y + 2048;
    } else {
        c.m = 2; c.bg = b - GZ_IN - GZ_REC; c.G = GZ_OUT; c.M = OUT_DIM; c.N = HID;
        c.W = Wout; c.ubuf = g_u + 4096; c.ybuf = g_y + 4096;
    }
    return c;
}

// Y-layout context (col split, 32 cols per block)
__device__ __forceinline__ PiCtx pi_ctxY(int b, const float* Win, const float* Wrec,
                                         const float* Wout) {
    PiCtx c;
    if (b < GY_IN) {
        c.m = 0; c.bg = b; c.G = GY_IN; c.M = HID; c.N = IN_DIM;
        c.W = Win; c.ubuf = g_u; c.ybuf = g_y;
    } else if (b < GY_IN + GY_REC) {
        c.m = 1; c.bg = b - GY_IN; c.G = GY_REC; c.M = HID; c.N = HID;
        c.W = Wrec; c.ubuf = g_u + 2048; c.ybuf = g_y + 2048;
    } else {
        c.m = 2; c.bg = b - GY_IN - GY_REC; c.G = GY_OUT; c.M = OUT_DIM; c.N = HID;
        c.W = Wout; c.ubuf = g_u + 4096; c.ybuf = g_y + 4096;
    }
    return c;
}

__device__ __forceinline__ float block_sum_partials(const float* part, int G, float* red) {
    int t = threadIdx.x;
    red[t] = (t < G) ? part[t] : 0.0f;
    __syncthreads();
#pragma unroll
    for (int s = 128; s > 0; s >>= 1) {
        if (t < s) red[t] += red[t + s];
        __syncthreads();
    }
    float v = red[0];
    __syncthreads();
    return v;
}

__global__ void pi_init() {
    int t = threadIdx.x;
    for (int i = t; i < 2048; i += 256) {
        g_u[i] = 1.0f;
        g_u[2048 + i] = 1.0f;
        if (i < OUT_DIM) g_u[4096 + i] = 1.0f;
    }
    for (int g = t; g < 256; g += 256) {
        g_partZ[0][g] = 0.0f; g_partZ[1][g] = 0.0f; g_partZ[2][g] = 0.0f;
    }
    if (t == 0) {
        g_partZ[0][0] = (float)HID;
        g_partZ[1][0] = (float)HID;
        g_partZ[2][0] = (float)OUT_DIM;
    }
}

// phaseY: ybuf = W^T u_hat. 32 consecutive cols per block -> fully coalesced.
// lanes = consecutive cols; 8 segments of rows per block; 8-row MLP unroll.
__global__ void pi_phaseY(const float* __restrict__ Win, const float* __restrict__ Wrec,
                          const float* __restrict__ Wout) {
    PiCtx c = pi_ctxY(blockIdx.x, Win, Wrec, Wout);
    int gz = (c.m == 1) ? GZ_REC : ((c.m == 0) ? GZ_IN : GZ_OUT);
    __shared__ float red[256];
    __shared__ float ssq[32];
    float ss = block_sum_partials(g_partZ[c.m], gz, red);
    float su = 1.0f / (sqrtf(ss) + EPSN);

    int cl = threadIdx.x & 31;          // column lane (coalesced)
    int seg = threadIdx.x >> 5;         // 8 row segments
    int col = c.bg * 32 + cl;
    int rps = (c.M + 7) / 8;            // rows per segment (2048->256, 1000->125)
    int r0 = seg * rps;
    int iend = min(r0 + rps, c.M);

    const float* Wc = c.W + col;
    float a0=0.f,a1=0.f,a2=0.f,a3=0.f,a4=0.f,a5=0.f,a6=0.f,a7=0.f;
    int i = r0;
    for (; i + 7 < iend; i += 8) {
        a0 += Wc[(size_t)(i+0)*c.N] * c.ubuf[i+0];
        a1 += Wc[(size_t)(i+1)*c.N] * c.ubuf[i+1];
        a2 += Wc[(size_t)(i+2)*c.N] * c.ubuf[i+2];
        a3 += Wc[(size_t)(i+3)*c.N] * c.ubuf[i+3];
        a4 += Wc[(size_t)(i+4)*c.N] * c.ubuf[i+4];
        a5 += Wc[(size_t)(i+5)*c.N] * c.ubuf[i+5];
        a6 += Wc[(size_t)(i+6)*c.N] * c.ubuf[i+6];
        a7 += Wc[(size_t)(i+7)*c.N] * c.ubuf[i+7];
    }
    for (; i < iend; ++i) a0 += Wc[(size_t)i*c.N] * c.ubuf[i];
    float acc = ((a0+a1)+(a2+a3)) + ((a4+a5)+(a6+a7));

    red[threadIdx.x] = acc;
    __syncthreads();
    if (seg == 0) {
        float tot = 0.0f;
        for (int s = 0; s < 8; ++s) tot += red[cl + s * 32];
        float yv = tot * su;
        c.ybuf[col] = yv;
        ssq[cl] = yv * yv;
    }
    __syncthreads();
    if (threadIdx.x == 0) {
        float p = 0.0f;
        for (int q = 0; q < 32; ++q) p += ssq[q];
        g_partY[c.m][c.bg] = p;
    }
}

// phaseZ: ubuf = W v_hat. Warp per row (coalesced), 8-way MLP unroll.
__global__ void pi_phaseZ(const float* __restrict__ Win, const float* __restrict__ Wrec,
                          const float* __restrict__ Wout) {
    PiCtx c = pi_ctxZ(blockIdx.x, Win, Wrec, Wout);
    int gy = (c.m == 1) ? GY_REC : ((c.m == 0) ? GY_IN : GY_OUT);
    __shared__ float red[256];
    float ss = block_sum_partials(g_partY[c.m], gy, red);
    float sv = 1.0f / (sqrtf(ss) + EPSN);

    int warp = threadIdx.x >> 5, lane = threadIdx.x & 31;
    int rpb = (c.M + c.G - 1) / c.G;
    int rend = min(c.bg * rpb + rpb, c.M);

    float acc2 = 0.0f;
    for (int r = c.bg * rpb + warp; r < rend; r += 8) {
        const float* row = c.W + (size_t)r * c.N;
        float a0=0.f,a1=0.f,a2=0.f,a3=0.f,a4=0.f,a5=0.f,a6=0.f,a7=0.f;
        for (int j = lane; j < c.N; j += 256) {   // N in {1024,2048}: /256 exact
            a0 += row[j      ] * c.ybuf[j      ];
            a1 += row[j +  32] * c.ybuf[j +  32];
            a2 += row[j +  64] * c.ybuf[j +  64];
            a3 += row[j +  96] * c.ybuf[j +  96];
            a4 += row[j + 128] * c.ybuf[j + 128];
            a5 += row[j + 160] * c.ybuf[j + 160];
            a6 += row[j + 192] * c.ybuf[j + 192];
            a7 += row[j + 224] * c.ybuf[j + 224];
        }
        float a = ((a0+a1)+(a2+a3)) + ((a4+a5)+(a6+a7));
        for (int o = 16; o; o >>= 1) a += __shfl_down_sync(0xffffffffu, a, o);
        if (lane == 0) {
            float z = a * sv;
            c.ubuf[r] = z;
            acc2 += z * z;
        }
    }
    __shared__ float wsq[8];
    if (lane == 0) wsq[warp] = acc2;
    __syncthreads();
    if (threadIdx.x == 0) {
        float p = 0.0f;
        for (int w = 0; w < 8; ++w) p += wsq[w];
        g_partZ[c.m][c.bg] = p;
    }
}

__global__ void pi_sigma(const float* __restrict__ Win, const float* __restrict__ Wrec,
                         const float* __restrict__ Wout) {
    PiCtx c = pi_ctxZ(blockIdx.x, Win, Wrec, Wout);
    int gy = (c.m == 1) ? GY_REC : ((c.m == 0) ? GY_IN : GY_OUT);
    __shared__ float red[256];
    float ssz = block_sum_partials(g_partZ[c.m], c.G, red);
    float ssy = block_sum_partials(g_partY[c.m], gy, red);
    float su = 1.0f / (sqrtf(ssz) + EPSN);
    float sv = 1.0f / (sqrtf(ssy) + EPSN);

    int warp = threadIdx.x >> 5, lane = threadIdx.x & 31;
    int rpb = (c.M + c.G - 1) / c.G;
    int rend = min(c.bg * rpb + rpb, c.M);

    float contrib = 0.0f;
    for (int r = c.bg * rpb + warp; r < rend; r += 8) {
        const float* row = c.W + (size_t)r * c.N;
        float a0=0.f,a1=0.f,a2=0.f,a3=0.f,a4=0.f,a5=0.f,a6=0.f,a7=0.f;
        for (int j = lane; j < c.N; j += 256) {
            a0 += row[j      ] * c.ybuf[j      ];
            a1 += row[j +  32] * c.ybuf[j +  32];
            a2 += row[j +  64] * c.ybuf[j +  64];
            a3 += row[j +  96] * c.ybuf[j +  96];
            a4 += row[j + 128] * c.ybuf[j + 128];
            a5 += row[j + 160] * c.ybuf[j + 160];
            a6 += row[j + 192] * c.ybuf[j + 192];
            a7 += row[j + 224] * c.ybuf[j + 224];
        }
        float a = ((a0+a1)+(a2+a3)) + ((a4+a5)+(a6+a7));
        for (int o = 16; o; o >>= 1) a += __shfl_down_sync(0xffffffffu, a, o);
        if (lane == 0) contrib += (su * c.ubuf[r]) * (sv * a);
    }
    __shared__ float wsq[8];
    if (lane == 0) wsq[warp] = contrib;
    __syncthreads();
    if (threadIdx.x == 0) {
        float p = 0.0f;
        for (int w = 0; w < 8; ++w) p += wsq[w];
        g_sigpart[c.m][c.bg] = p;
    }
}

__global__ void pi_finalize() {
    int m = threadIdx.x;
    if (m < 3) {
        int G = (m == 1) ? GZ_REC : ((m == 0) ? GZ_IN : GZ_OUT);
        float s = 0.0f;
        for (int g = 0; g < G; ++g) s += g_sigpart[m][g];
        g_inv_sigma[m] = 1.0f / s;
    }
}

// ---------------------------------------------------------------------------
// 3x-bf16 mma.sync GEMM on pre-packed operands.
// KEY CHANGE vs R8: split-term-major MMA issue order. Each accumulator's
// 3 HMMAs (hh, hl, lh) are separated by 16 independent issues so the
// acc-chain dependency latency is fully covered.
// ---------------------------------------------------------------------------
#define BM 128
#define BN 128
#define BKT 32
#define PSTRIDE 20

__device__ __forceinline__ void mma16(float* c, uint32_t a0, uint32_t a1, uint32_t a2,
                                      uint32_t a3, uint32_t b0, uint32_t b1) {
    asm volatile(
        "mma.sync.aligned.m16n8k16.row.col.f32.bf16.bf16.f32 "
        "{%0,%1,%2,%3}, {%4,%5,%6,%7}, {%8,%9}, {%0,%1,%2,%3};"
        : "+f"(c[0]), "+f"(c[1]), "+f"(c[2]), "+f"(c[3])
        : "r"(a0), "r"(a1), "r"(a2), "r"(a3), "r"(b0), "r"(b1));
}

template <int OKIND>
__global__ __launch_bounds__(256)
void gemm_pk(const uint2* __restrict__ A, const uint2* __restrict__ B,
             const float* __restrict__ bias, const float* __restrict__ bias2,
             const float* __restrict__ raw, float* __restrict__ Cf,
             uint2* __restrict__ Cp, int M, int N, int Nreal, int K) {
    __shared__ __align__(16) uint2 As[BM * PSTRIDE];
    __shared__ __align__(16) uint2 Bs[BN * PSTRIDE];

    int tid = threadIdx.x;
    int bm = blockIdx.y * BM, bn = blockIdx.x * BN;
    int Kp = K >> 1;

    int rowq[4], uq[4];
#pragma unroll
    for (int q = 0; q < 4; ++q) {
        int idx = tid + q * 256;
        rowq[q] = idx >> 3;
        uq[q] = (idx & 7) * 2;
    }

    int warp = tid >> 5, lane = tid & 31;
    int wm = (warp & 1) * 64;
    int wn = (warp >> 1) * 32;
    int g = lane >> 2;
    int t = lane & 3;

    float acc[4][4][4];
#pragma unroll
    for (int i = 0; i < 4; ++i)
#pragma unroll
        for (int j = 0; j < 4; ++j)
#pragma unroll
            for (int q = 0; q < 4; ++q) acc[i][j][q] = 0.0f;

    uint4 pa[4], pb[4];
#pragma unroll
    for (int q = 0; q < 4; ++q) {
        pa[q] = *(const uint4*)(A + (size_t)(bm + rowq[q]) * Kp + uq[q]);
        pb[q] = *(const uint4*)(B + (size_t)(bn + rowq[q]) * Kp + uq[q]);
    }

    int KT = K / BKT;
    for (int kt = 0; kt < KT; ++kt) {
        __syncthreads();
#pragma unroll
        for (int q = 0; q < 4; ++q) {
            *(uint4*)&As[rowq[q] * PSTRIDE + uq[q]] = pa[q];
            *(uint4*)&Bs[rowq[q] * PSTRIDE + uq[q]] = pb[q];
        }
        __syncthreads();

        if (kt + 1 < KT) {
            int off = (kt + 1) * 16;
#pragma unroll
            for (int q = 0; q < 4; ++q) {
                pa[q] = *(const uint4*)(A + (size_t)(bm + rowq[q]) * Kp + off + uq[q]);
                pb[q] = *(const uint4*)(B + (size_t)(bn + rowq[q]) * Kp + off + uq[q]);
            }
        }

#pragma unroll
        for (int kp = 0; kp < 16; kp += 8) {
            uint2 Af[4][4];
            uint2 Bf[4][2];
#pragma unroll
            for (int mf = 0; mf < 4; ++mf) {
                int rb = wm + mf * 16 + g;
                Af[mf][0] = As[rb * PSTRIDE + kp + t];
                Af[mf][1] = As[(rb + 8) * PSTRIDE + kp + t];
                Af[mf][2] = As[rb * PSTRIDE + kp + t + 4];
                Af[mf][3] = As[(rb + 8) * PSTRIDE + kp + t + 4];
            }
#pragma unroll
            for (int nf = 0; nf < 4; ++nf) {
                int cb = wn + nf * 8 + g;
                Bf[nf][0] = Bs[cb * PSTRIDE + kp + t];
                Bf[nf][1] = Bs[cb * PSTRIDE + kp + t + 4];
            }
            // term hh: 16 independent HMMAs
#pragma unroll
            for (int nf = 0; nf < 4; ++nf)
#pragma unroll
                for (int mf = 0; mf < 4; ++mf)
                    mma16(acc[mf][nf], Af[mf][0].x, Af[mf][1].x, Af[mf][2].x, Af[mf][3].x,
                          Bf[nf][0].x, Bf[nf][1].x);
            // term hl
#pragma unroll
            for (int nf = 0; nf < 4; ++nf)
#pragma unroll
                for (int mf = 0; mf < 4; ++mf)
                    mma16(acc[mf][nf], Af[mf][0].x, Af[mf][1].x, Af[mf][2].x, Af[mf][3].x,
                          Bf[nf][0].y, Bf[nf][1].y);
            // term lh
#pragma unroll
            for (int nf = 0; nf < 4; ++nf)
#pragma unroll
                for (int mf = 0; mf < 4; ++mf)
                    mma16(acc[mf][nf], Af[mf][0].y, Af[mf][1].y, Af[mf][2].y, Af[mf][3].y,
                          Bf[nf][0].x, Bf[nf][1].x);
        }
    }

    // ---- epilogue ----
    float s_main = (OKIND == 1) ? g_inv_sigma[1] : ((OKIND == 2) ? g_inv_sigma[2] : 1.0f);
    float s_in = (OKIND == 1) ? g_inv_sigma[0] : 0.0f;
#pragma unroll
    for (int mf = 0; mf < 4; ++mf) {
        int r0 = bm + wm + mf * 16 + g;
#pragma unroll
        for (int nf = 0; nf < 4; ++nf) {
            int c0 = bn + wn + nf * 8 + 2 * t;
            float* a = acc[mf][nf];
#pragma unroll
            for (int half = 0; half < 2; ++half) {
                int rr = r0 + half * 8;
                float v0 = a[half * 2 + 0];
                float v1 = a[half * 2 + 1];
                if (OKIND == 0) {
                    size_t base = (size_t)rr * N + c0;
                    float2 o; o.x = v0; o.y = v1;
                    *(float2*)(Cf + base) = o;
                } else if (OKIND == 1) {
                    size_t base = (size_t)rr * N + c0;
                    float2 rw = *(const float2*)(raw + base);
                    v0 = tanhf(v0 * s_main + bias[c0] + rw.x * s_in + bias2[c0]);
                    v1 = tanhf(v1 * s_main + bias[c0 + 1] + rw.y * s_in + bias2[c0 + 1]);
                    uint32_t hi, lo;
                    split2(v0, v1, hi, lo);
                    Cp[((size_t)rr * N + c0) >> 1] = make_uint2(hi, lo);
                } else {
                    size_t base = (size_t)rr * Nreal;
                    if (c0 < Nreal)     Cf[base + c0]     = v0 * s_main + bias[c0];
                    if (c0 + 1 < Nreal) Cf[base + c0 + 1] = v1 * s_main + bias[c0 + 1];
                }
            }
        }
    }
}

// Step 1 (h0 = 0): h_packed = split( tanh(raw*s_in + b_in + b_rec) )
__global__ void step1_kernel(const float* __restrict__ xpraw, const float* __restrict__ bin,
                             const float* __restrict__ brec, uint2* __restrict__ hp) {
    size_t i = ((size_t)blockIdx.x * blockDim.x + threadIdx.x) * 4;
    float s_in = g_inv_sigma[0];
    float4 v = *(const float4*)(xpraw + i);
    int col = (int)(i & (HID - 1));
    v.x = tanhf(v.x * s_in + bin[col + 0] + brec[col + 0]);
    v.y = tanhf(v.y * s_in + bin[col + 1] + brec[col + 1]);
    v.z = tanhf(v.z * s_in + bin[col + 2] + brec[col + 2]);
    v.w = tanhf(v.w * s_in + bin[col + 3] + brec[col + 3]);
    uint32_t h01, l01, h23, l23;
    split2(v.x, v.y, h01, l01);
    split2(v.z, v.w, h23, l23);
    *(uint4*)(hp + (i >> 1)) = make_uint4(h01, l01, h23, l23);
}

// ---------------------------------------------------------------------------
// Launch
// ---------------------------------------------------------------------------
extern "C" void kernel_launch(void* const* d_in, const int* in_sizes, int n_in,
                              void* d_out, int out_size) {
    (void)in_sizes; (void)n_in; (void)out_size;
    const float* x    = (const float*)d_in[0];
    const float* Win  = (const float*)d_in[1];
    const float* bin  = (const float*)d_in[2];
    const float* Wrec = (const float*)d_in[3];
    const float* brec = (const float*)d_in[4];
    const float* Wout = (const float*)d_in[5];
    const float* bout = (const float*)d_in[6];
    float* out = (float*)d_out;

    uint2 *xp, *winp, *wrecp, *woutp, *hp0, *hp1;
    float* xraw;
    cudaGetSymbolAddress((void**)&xp, g_xp);
    cudaGetSymbolAddress((void**)&winp, g_Winp);
    cudaGetSymbolAddress((void**)&wrecp, g_Wrecp);
    cudaGetSymbolAddress((void**)&woutp, g_Woutp);
    cudaGetSymbolAddress((void**)&xraw, g_xraw);
    cudaGetSymbolAddress((void**)&hp0, g_hp0);
    cudaGetSymbolAddress((void**)&hp1, g_hp1);

    pi_init<<<1, 256>>>();
    prepack<<<(BATCH * IN_DIM / 4) / 256, 256>>>(x, xp, BATCH * IN_DIM / 4);
    prepack<<<(HID * IN_DIM / 4) / 256, 256>>>(Win, winp, HID * IN_DIM / 4);
    prepack<<<(HID * HID / 4) / 256, 256>>>(Wrec, wrecp, HID * HID / 4);
    prepack_pad<<<(NPAD_OUT * HID / 4) / 256, 256>>>(Wout, woutp, OUT_DIM, HID / 4,
                                                     NPAD_OUT * HID / 4);
    // raw xproj GEMM (sigma-independent)
    gemm_pk<0><<<dim3(HID / BN, BATCH / BM), 256>>>(
        xp, winp, nullptr, nullptr, nullptr, xraw, nullptr, BATCH, HID, HID, IN_DIM);

    // --- spectral norms (power iteration, fp32, exact reference sequence) ---
    for (int it = 0; it < NPI; ++it) {
        pi_phaseY<<<NBY, 256>>>(Win, Wrec, Wout);
        pi_phaseZ<<<NBZ, 256>>>(Win, Wrec, Wout);
    }
    pi_phaseY<<<NBY, 256>>>(Win, Wrec, Wout);   // final v = norm(W^T u)
    pi_sigma<<<NBZ, 256>>>(Win, Wrec, Wout);    // sigma = u . (W v)
    pi_finalize<<<1, 32>>>();

    // step 1
    step1_kernel<<<(BATCH * HID) / (256 * 4), 256>>>(xraw, bin, brec, hp0);

    // steps 2..30
    uint2* hin = hp0;
    uint2* hout = hp1;
    for (int s = 1; s < STEPS; ++s) {
        gemm_pk<1><<<dim3(HID / BN, BATCH / BM), 256>>>(
            hin, wrecp, brec, bin, xraw, nullptr, hout, BATCH, HID, HID, HID);
        uint2* tmp = hin; hin = hout; hout = tmp;
    }

    // out GEMM (B padded to 1024 rows; stores col-guarded)
    gemm_pk<2><<<dim3(NPAD_OUT / BN, BATCH / BM), 256>>>(
        hin, woutp, bout, nullptr, nullptr, out, nullptr, BATCH, NPAD_OUT, OUT_DIM, HID);
}

// round 11
// speedup vs baseline: 2.2895x; 1.5219x over previous
#include <cuda_runtime.h>
#include <cuda_fp16.h>
#include <cstdint>

// ---------------------------------------------------------------------------
// Problem constants
// ---------------------------------------------------------------------------
#define IN_DIM   1024
#define HID      2048
#define OUT_DIM  1000
#define NPAD_OUT 1024
#define BATCH    4096
#define STEPS    30
#define NPI      30
#define EPSN     1e-12f

#define GZ_IN  128
#define GZ_REC 256
#define GZ_OUT 64
#define NBZ (GZ_IN + GZ_REC + GZ_OUT)
#define GY_IN  32
#define GY_REC 64
#define GY_OUT 64
#define NBY (GY_IN + GY_REC + GY_OUT)

// ---------------------------------------------------------------------------
// Device scratch
// ---------------------------------------------------------------------------
__device__ float g_u[6144];
__device__ float g_y[6144];
__device__ float g_partY[3][64];
__device__ float g_partZ[3][256];
__device__ float g_sigpart[3][256];
__device__ float g_inv_sigma[3];

// bf16 hi/lo pairs (3-term xproj GEMM)
__device__ uint2 g_xp[(size_t)BATCH * IN_DIM / 2];
__device__ uint2 g_Winp[(size_t)HID * IN_DIM / 2];
// fp16 hi/lo pairs (2-term GEMMs)
__device__ uint2 g_Wrecp[(size_t)HID * HID / 2];
__device__ uint2 g_Woutp[(size_t)NPAD_OUT * HID / 2];
// fp32 raw xproj; fp16 h ping-pong (fp16x2 per uint32)
__device__ float g_xraw[(size_t)BATCH * HID];
__device__ uint32_t g_hf0[(size_t)BATCH * HID / 2];
__device__ uint32_t g_hf1[(size_t)BATCH * HID / 2];

// ---------------------------------------------------------------------------
// split helpers
// ---------------------------------------------------------------------------
__device__ __forceinline__ void split2_bf(float x0, float x1, uint32_t& hi, uint32_t& lo) {
    uint32_t h;
    asm("cvt.rn.bf16x2.f32 %0, %1, %2;" : "=r"(h) : "f"(x1), "f"(x0));
    float h0 = __uint_as_float(h << 16);
    float h1 = __uint_as_float(h & 0xffff0000u);
    float r0 = x0 - h0, r1 = x1 - h1;
    uint32_t l;
    asm("cvt.rn.bf16x2.f32 %0, %1, %2;" : "=r"(l) : "f"(r1), "f"(r0));
    hi = h; lo = l;
}

__device__ __forceinline__ void split2_hf(float x0, float x1, uint32_t& hi, uint32_t& lo) {
    __half a = __float2half_rn(x0), b = __float2half_rn(x1);
    __half2 hh = __halves2half2(a, b);             // .x (low bits) = x0
    float r0 = x0 - __half2float(a), r1 = x1 - __half2float(b);
    __half2 ll = __halves2half2(__float2half_rn(r0), __float2half_rn(r1));
    hi = *(uint32_t*)&hh; lo = *(uint32_t*)&ll;
}

__device__ __forceinline__ uint32_t pack_hf(float x0, float x1) {
    __half2 hh = __halves2half2(__float2half_rn(x0), __float2half_rn(x1));
    return *(uint32_t*)&hh;
}

// ---------------------------------------------------------------------------
// Prepack kernels
// ---------------------------------------------------------------------------
__global__ void prepack_bf(const float* __restrict__ src, uint2* __restrict__ dst, int n4) {
    int i = blockIdx.x * 256 + threadIdx.x;
    if (i < n4) {
        float4 v = ((const float4*)src)[i];
        uint32_t h01, l01, h23, l23;
        split2_bf(v.x, v.y, h01, l01);
        split2_bf(v.z, v.w, h23, l23);
        ((uint4*)dst)[i] = make_uint4(h01, l01, h23, l23);
    }
}

__global__ void prepack_hf(const float* __restrict__ src, uint2* __restrict__ dst, int n4) {
    int i = blockIdx.x * 256 + threadIdx.x;
    if (i < n4) {
        float4 v = ((const float4*)src)[i];
        uint32_t h01, l01, h23, l23;
        split2_hf(v.x, v.y, h01, l01);
        split2_hf(v.z, v.w, h23, l23);
        ((uint4*)dst)[i] = make_uint4(h01, l01, h23, l23);
    }
}

__global__ void prepack_hf_pad(const float* __restrict__ src, uint2* __restrict__ dst,
                               int src_rows, int K4, int n4) {
    int i = blockIdx.x * 256 + threadIdx.x;
    if (i < n4) {
        int row = i / K4;
        uint4 o = make_uint4(0u, 0u, 0u, 0u);
        if (row < src_rows) {
            float4 v = ((const float4*)src)[i];
            uint32_t h01, l01, h23, l23;
            split2_hf(v.x, v.y, h01, l01);
            split2_hf(v.z, v.w, h23, l23);
            o = make_uint4(h01, l01, h23, l23);
        }
        ((uint4*)dst)[i] = o;
    }
}

// ---------------------------------------------------------------------------
// Power iteration (fp32, reference-exact sequence)
// ---------------------------------------------------------------------------
struct PiCtx { int m, bg, G, M, N; const float* W; float* ubuf; float* ybuf; };

__device__ __forceinline__ PiCtx pi_ctxZ(int b, const float* Win, const float* Wrec,
                                         const float* Wout) {
    PiCtx c;
    if (b < GZ_IN) {
        c.m = 0; c.bg = b; c.G = GZ_IN; c.M = HID; c.N = IN_DIM;
        c.W = Win; c.ubuf = g_u; c.ybuf = g_y;
    } else if (b < GZ_IN + GZ_REC) {
        c.m = 1; c.bg = b - GZ_IN; c.G = GZ_REC; c.M = HID; c.N = HID;
        c.W = Wrec; c.ubuf = g_u + 2048; c.ybuf = g_y + 2048;
    } else {
        c.m = 2; c.bg = b - GZ_IN - GZ_REC; c.G = GZ_OUT; c.M = OUT_DIM; c.N = HID;
        c.W = Wout; c.ubuf = g_u + 4096; c.ybuf = g_y + 4096;
    }
    return c;
}

__device__ __forceinline__ PiCtx pi_ctxY(int b, const float* Win, const float* Wrec,
                                         const float* Wout) {
    PiCtx c;
    if (b < GY_IN) {
        c.m = 0; c.bg = b; c.G = GY_IN; c.M = HID; c.N = IN_DIM;
        c.W = Win; c.ubuf = g_u; c.ybuf = g_y;
    } else if (b < GY_IN + GY_REC) {
        c.m = 1; c.bg = b - GY_IN; c.G = GY_REC; c.M = HID; c.N = HID;
        c.W = Wrec; c.ubuf = g_u + 2048; c.ybuf = g_y + 2048;
    } else {
        c.m = 2; c.bg = b - GY_IN - GY_REC; c.G = GY_OUT; c.M = OUT_DIM; c.N = HID;
        c.W = Wout; c.ubuf = g_u + 4096; c.ybuf = g_y + 4096;
    }
    return c;
}

__device__ __forceinline__ float block_sum_partials(const float* part, int G, float* red) {
    int t = threadIdx.x;
    red[t] = (t < G) ? part[t] : 0.0f;
    __syncthreads();
#pragma unroll
    for (int s = 128; s > 0; s >>= 1) {
        if (t < s) red[t] += red[t + s];
        __syncthreads();
    }
    float v = red[0];
    __syncthreads();
    return v;
}

__global__ void pi_init() {
    int t = threadIdx.x;
    for (int i = t; i < 2048; i += 256) {
        g_u[i] = 1.0f;
        g_u[2048 + i] = 1.0f;
        if (i < OUT_DIM) g_u[4096 + i] = 1.0f;
    }
    for (int g = t; g < 256; g += 256) {
        g_partZ[0][g] = 0.0f; g_partZ[1][g] = 0.0f; g_partZ[2][g] = 0.0f;
    }
    if (t == 0) {
        g_partZ[0][0] = (float)HID;
        g_partZ[1][0] = (float)HID;
        g_partZ[2][0] = (float)OUT_DIM;
    }
}

__global__ void pi_phaseY(const float* __restrict__ Win, const float* __restrict__ Wrec,
                          const float* __restrict__ Wout) {
    PiCtx c = pi_ctxY(blockIdx.x, Win, Wrec, Wout);
    int gz = (c.m == 1) ? GZ_REC : ((c.m == 0) ? GZ_IN : GZ_OUT);
    __shared__ float red[256];
    __shared__ float ssq[32];
    float ss = block_sum_partials(g_partZ[c.m], gz, red);
    float su = 1.0f / (sqrtf(ss) + EPSN);

    int cl = threadIdx.x & 31;
    int seg = threadIdx.x >> 5;
    int col = c.bg * 32 + cl;
    int rps = (c.M + 7) / 8;
    int r0 = seg * rps;
    int iend = min(r0 + rps, c.M);

    const float* Wc = c.W + col;
    float a0=0.f,a1=0.f,a2=0.f,a3=0.f,a4=0.f,a5=0.f,a6=0.f,a7=0.f;
    int i = r0;
    for (; i + 7 < iend; i += 8) {
        a0 += Wc[(size_t)(i+0)*c.N] * c.ubuf[i+0];
        a1 += Wc[(size_t)(i+1)*c.N] * c.ubuf[i+1];
        a2 += Wc[(size_t)(i+2)*c.N] * c.ubuf[i+2];
        a3 += Wc[(size_t)(i+3)*c.N] * c.ubuf[i+3];
        a4 += Wc[(size_t)(i+4)*c.N] * c.ubuf[i+4];
        a5 += Wc[(size_t)(i+5)*c.N] * c.ubuf[i+5];
        a6 += Wc[(size_t)(i+6)*c.N] * c.ubuf[i+6];
        a7 += Wc[(size_t)(i+7)*c.N] * c.ubuf[i+7];
    }
    for (; i < iend; ++i) a0 += Wc[(size_t)i*c.N] * c.ubuf[i];
    float acc = ((a0+a1)+(a2+a3)) + ((a4+a5)+(a6+a7));

    red[threadIdx.x] = acc;
    __syncthreads();
    if (seg == 0) {
        float tot = 0.0f;
        for (int s = 0; s < 8; ++s) tot += red[cl + s * 32];
        float yv = tot * su;
        c.ybuf[col] = yv;
        ssq[cl] = yv * yv;
    }
    __syncthreads();
    if (threadIdx.x == 0) {
        float p = 0.0f;
        for (int q = 0; q < 32; ++q) p += ssq[q];
        g_partY[c.m][c.bg] = p;
    }
}

__global__ void pi_phaseZ(const float* __restrict__ Win, const float* __restrict__ Wrec,
                          const float* __restrict__ Wout) {
    PiCtx c = pi_ctxZ(blockIdx.x, Win, Wrec, Wout);
    int gy = (c.m == 1) ? GY_REC : ((c.m == 0) ? GY_IN : GY_OUT);
    __shared__ float red[256];
    float ss = block_sum_partials(g_partY[c.m], gy, red);
    float sv = 1.0f / (sqrtf(ss) + EPSN);

    int warp = threadIdx.x >> 5, lane = threadIdx.x & 31;
    int rpb = (c.M + c.G - 1) / c.G;
    int rend = min(c.bg * rpb + rpb, c.M);

    float acc2 = 0.0f;
    for (int r = c.bg * rpb + warp; r < rend; r += 8) {
        const float* row = c.W + (size_t)r * c.N;
        float a0=0.f,a1=0.f,a2=0.f,a3=0.f,a4=0.f,a5=0.f,a6=0.f,a7=0.f;
        for (int j = lane; j < c.N; j += 256) {
            a0 += row[j      ] * c.ybuf[j      ];
            a1 += row[j +  32] * c.ybuf[j +  32];
            a2 += row[j +  64] * c.ybuf[j +  64];
            a3 += row[j +  96] * c.ybuf[j +  96];
            a4 += row[j + 128] * c.ybuf[j + 128];
            a5 += row[j + 160] * c.ybuf[j + 160];
            a6 += row[j + 192] * c.ybuf[j + 192];
            a7 += row[j + 224] * c.ybuf[j + 224];
        }
        float a = ((a0+a1)+(a2+a3)) + ((a4+a5)+(a6+a7));
        for (int o = 16; o; o >>= 1) a += __shfl_down_sync(0xffffffffu, a, o);
        if (lane == 0) {
            float z = a * sv;
            c.ubuf[r] = z;
            acc2 += z * z;
        }
    }
    __shared__ float wsq[8];
    if (lane == 0) wsq[warp] = acc2;
    __syncthreads();
    if (threadIdx.x == 0) {
        float p = 0.0f;
        for (int w = 0; w < 8; ++w) p += wsq[w];
        g_partZ[c.m][c.bg] = p;
    }
}

__global__ void pi_sigma(const float* __restrict__ Win, const float* __restrict__ Wrec,
                         const float* __restrict__ Wout) {
    PiCtx c = pi_ctxZ(blockIdx.x, Win, Wrec, Wout);
    int gy = (c.m == 1) ? GY_REC : ((c.m == 0) ? GY_IN : GY_OUT);
    __shared__ float red[256];
    float ssz = block_sum_partials(g_partZ[c.m], c.G, red);
    float ssy = block_sum_partials(g_partY[c.m], gy, red);
    float su = 1.0f / (sqrtf(ssz) + EPSN);
    float sv = 1.0f / (sqrtf(ssy) + EPSN);

    int warp = threadIdx.x >> 5, lane = threadIdx.x & 31;
    int rpb = (c.M + c.G - 1) / c.G;
    int rend = min(c.bg * rpb + rpb, c.M);

    float contrib = 0.0f;
    for (int r = c.bg * rpb + warp; r < rend; r += 8) {
        const float* row = c.W + (size_t)r * c.N;
        float a0=0.f,a1=0.f,a2=0.f,a3=0.f,a4=0.f,a5=0.f,a6=0.f,a7=0.f;
        for (int j = lane; j < c.N; j += 256) {
            a0 += row[j      ] * c.ybuf[j      ];
            a1 += row[j +  32] * c.ybuf[j +  32];
            a2 += row[j +  64] * c.ybuf[j +  64];
            a3 += row[j +  96] * c.ybuf[j +  96];
            a4 += row[j + 128] * c.ybuf[j + 128];
            a5 += row[j + 160] * c.ybuf[j + 160];
            a6 += row[j + 192] * c.ybuf[j + 192];
            a7 += row[j + 224] * c.ybuf[j + 224];
        }
        float a = ((a0+a1)+(a2+a3)) + ((a4+a5)+(a6+a7));
        for (int o = 16; o; o >>= 1) a += __shfl_down_sync(0xffffffffu, a, o);
        if (lane == 0) contrib += (su * c.ubuf[r]) * (sv * a);
    }
    __shared__ float wsq[8];
    if (lane == 0) wsq[warp] = contrib;
    __syncthreads();
    if (threadIdx.x == 0) {
        float p = 0.0f;
        for (int w = 0; w < 8; ++w) p += wsq[w];
        g_sigpart[c.m][c.bg] = p;
    }
}

__global__ void pi_finalize() {
    int m = threadIdx.x;
    if (m < 3) {
        int G = (m == 1) ? GZ_REC : ((m == 0) ? GZ_IN : GZ_OUT);
        float s = 0.0f;
        for (int g = 0; g < G; ++g) s += g_sigpart[m][g];
        g_inv_sigma[m] = 1.0f / s;
    }
}

// ---------------------------------------------------------------------------
// MMA wrappers
// ---------------------------------------------------------------------------
__device__ __forceinline__ void mma_bf(float* c, uint32_t a0, uint32_t a1, uint32_t a2,
                                       uint32_t a3, uint32_t b0, uint32_t b1) {
    asm volatile(
        "mma.sync.aligned.m16n8k16.row.col.f32.bf16.bf16.f32 "
        "{%0,%1,%2,%3}, {%4,%5,%6,%7}, {%8,%9}, {%0,%1,%2,%3};"
        : "+f"(c[0]), "+f"(c[1]), "+f"(c[2]), "+f"(c[3])
        : "r"(a0), "r"(a1), "r"(a2), "r"(a3), "r"(b0), "r"(b1));
}
__device__ __forceinline__ void mma_hf(float* c, uint32_t a0, uint32_t a1, uint32_t a2,
                                       uint32_t a3, uint32_t b0, uint32_t b1) {
    asm volatile(
        "mma.sync.aligned.m16n8k16.row.col.f32.f16.f16.f32 "
        "{%0,%1,%2,%3}, {%4,%5,%6,%7}, {%8,%9}, {%0,%1,%2,%3};"
        : "+f"(c[0]), "+f"(c[1]), "+f"(c[2]), "+f"(c[3])
        : "r"(a0), "r"(a1), "r"(a2), "r"(a3), "r"(b0), "r"(b1));
}

#define BM 128
#define BN 128
#define BKT 32
#define PSTRIDE 20     // uint2 per packed-pair row
#define ASTRIDE 80     // bytes per fp16 A row in smem (64 data + 16 pad)

// ---------------------------------------------------------------------------
// 3-term bf16 GEMM on packed pairs (xproj only): Cf = A.B^T raw fp32
// ---------------------------------------------------------------------------
__global__ __launch_bounds__(256)
void gemm_bf3(const uint2* __restrict__ A, const uint2* __restrict__ B,
              float* __restrict__ Cf, int N, int K) {
    __shared__ __align__(16) uint2 As[BM * PSTRIDE];
    __shared__ __align__(16) uint2 Bs[BN * PSTRIDE];

    int tid = threadIdx.x;
    int bm = blockIdx.y * BM, bn = blockIdx.x * BN;
    int Kp = K >> 1;

    int rowq[4], uq[4];
#pragma unroll
    for (int q = 0; q < 4; ++q) {
        int idx = tid + q * 256;
        rowq[q] = idx >> 3;
        uq[q] = (idx & 7) * 2;
    }

    int warp = tid >> 5, lane = tid & 31;
    int wm = (warp & 1) * 64;
    int wn = (warp >> 1) * 32;
    int g = lane >> 2;
    int t = lane & 3;

    float acc[4][4][4];
#pragma unroll
    for (int i = 0; i < 4; ++i)
#pragma unroll
        for (int j = 0; j < 4; ++j)
#pragma unroll
            for (int q = 0; q < 4; ++q) acc[i][j][q] = 0.0f;

    uint4 pa[4], pb[4];
#pragma unroll
    for (int q = 0; q < 4; ++q) {
        pa[q] = *(const uint4*)(A + (size_t)(bm + rowq[q]) * Kp + uq[q]);
        pb[q] = *(const uint4*)(B + (size_t)(bn + rowq[q]) * Kp + uq[q]);
    }

    int KT = K / BKT;
    for (int kt = 0; kt < KT; ++kt) {
        __syncthreads();
#pragma unroll
        for (int q = 0; q < 4; ++q) {
            *(uint4*)&As[rowq[q] * PSTRIDE + uq[q]] = pa[q];
            *(uint4*)&Bs[rowq[q] * PSTRIDE + uq[q]] = pb[q];
        }
        __syncthreads();

        if (kt + 1 < KT) {
            int off = (kt + 1) * 16;
#pragma unroll
            for (int q = 0; q < 4; ++q) {
                pa[q] = *(const uint4*)(A + (size_t)(bm + rowq[q]) * Kp + off + uq[q]);
                pb[q] = *(const uint4*)(B + (size_t)(bn + rowq[q]) * Kp + off + uq[q]);
            }
        }

#pragma unroll
        for (int kp = 0; kp < 16; kp += 8) {
            uint2 Af[4][4];
            uint2 Bf[4][2];
#pragma unroll
            for (int mf = 0; mf < 4; ++mf) {
                int rb = wm + mf * 16 + g;
                Af[mf][0] = As[rb * PSTRIDE + kp + t];
                Af[mf][1] = As[(rb + 8) * PSTRIDE + kp + t];
                Af[mf][2] = As[rb * PSTRIDE + kp + t + 4];
                Af[mf][3] = As[(rb + 8) * PSTRIDE + kp + t + 4];
            }
#pragma unroll
            for (int nf = 0; nf < 4; ++nf) {
                int cb = wn + nf * 8 + g;
                Bf[nf][0] = Bs[cb * PSTRIDE + kp + t];
                Bf[nf][1] = Bs[cb * PSTRIDE + kp + t + 4];
            }
#pragma unroll
            for (int nf = 0; nf < 4; ++nf)
#pragma unroll
                for (int mf = 0; mf < 4; ++mf)
                    mma_bf(acc[mf][nf], Af[mf][0].x, Af[mf][1].x, Af[mf][2].x, Af[mf][3].x,
                           Bf[nf][0].x, Bf[nf][1].x);
#pragma unroll
            for (int nf = 0; nf < 4; ++nf)
#pragma unroll
                for (int mf = 0; mf < 4; ++mf)
                    mma_bf(acc[mf][nf], Af[mf][0].x, Af[mf][1].x, Af[mf][2].x, Af[mf][3].x,
                           Bf[nf][0].y, Bf[nf][1].y);
#pragma unroll
            for (int nf = 0; nf < 4; ++nf)
#pragma unroll
                for (int mf = 0; mf < 4; ++mf)
                    mma_bf(acc[mf][nf], Af[mf][0].y, Af[mf][1].y, Af[mf][2].y, Af[mf][3].y,
                           Bf[nf][0].x, Bf[nf][1].x);
        }
    }

#pragma unroll
    for (int mf = 0; mf < 4; ++mf) {
        int r0 = bm + wm + mf * 16 + g;
#pragma unroll
        for (int nf = 0; nf < 4; ++nf) {
            int c0 = bn + wn + nf * 8 + 2 * t;
            float* a = acc[mf][nf];
#pragma unroll
            for (int half = 0; half < 2; ++half) {
                int rr = r0 + half * 8;
                float2 o; o.x = a[half * 2 + 0]; o.y = a[half * 2 + 1];
                *(float2*)(Cf + (size_t)rr * N + c0) = o;
            }
        }
    }
}

// ---------------------------------------------------------------------------
// 2-term fp16 GEMM: A plain fp16 (exact as stored), B fp16 hi/lo pair.
// OKIND 1: rec step -> fp16 h' = tanh(acc*s_rec + b_rec + raw*s_in + b_in)
// OKIND 2: out -> fp32, col-guarded, acc*s_out + bias
// ---------------------------------------------------------------------------
template <int OKIND>
__global__ __launch_bounds__(256)
void gemm_h2(const uint32_t* __restrict__ Ah, const uint2* __restrict__ B,
             const float* __restrict__ bias, const float* __restrict__ bias2,
             const float* __restrict__ raw, float* __restrict__ Cf,
             uint32_t* __restrict__ Cp, int N, int Nreal, int K) {
    __shared__ __align__(16) uint8_t AsB[BM * ASTRIDE];   // 10 KB fp16 A tile
    __shared__ __align__(16) uint2 Bs[BN * PSTRIDE];      // 20 KB packed B

    int tid = threadIdx.x;
    int bm = blockIdx.y * BM, bn = blockIdx.x * BN;
    int K8 = K >> 3;    // uint4 per A row
    int Kp = K >> 1;    // uint2 per B row

    // A fill map: 512 uint4 -> 2/thread. row=idx>>2, quad=idx&3 (16B units)
    int arow[2], aq[2];
#pragma unroll
    for (int q = 0; q < 2; ++q) {
        int idx = tid + q * 256;
        arow[q] = idx >> 2;
        aq[q] = idx & 3;
    }
    // B fill map: 1024 uint4 -> 4/thread
    int brow[4], buq[4];
#pragma unroll
    for (int q = 0; q < 4; ++q) {
        int idx = tid + q * 256;
        brow[q] = idx >> 3;
        buq[q] = (idx & 7) * 2;
    }

    int warp = tid >> 5, lane = tid & 31;
    int wm = (warp & 1) * 64;
    int wn = (warp >> 1) * 32;
    int g = lane >> 2;
    int t = lane & 3;

    float acc[4][4][4];
#pragma unroll
    for (int i = 0; i < 4; ++i)
#pragma unroll
        for (int j = 0; j < 4; ++j)
#pragma unroll
            for (int q = 0; q < 4; ++q) acc[i][j][q] = 0.0f;

    const uint4* A4 = (const uint4*)Ah;
    uint4 pa[2], pb[4];
#pragma unroll
    for (int q = 0; q < 2; ++q)
        pa[q] = A4[(size_t)(bm + arow[q]) * K8 + aq[q]];
#pragma unroll
    for (int q = 0; q < 4; ++q)
        pb[q] = *(const uint4*)(B + (size_t)(bn + brow[q]) * Kp + buq[q]);

    int KT = K / BKT;
    for (int kt = 0; kt < KT; ++kt) {
        __syncthreads();
#pragma unroll
        for (int q = 0; q < 2; ++q)
            *(uint4*)(AsB + arow[q] * ASTRIDE + aq[q] * 16) = pa[q];
#pragma unroll
        for (int q = 0; q < 4; ++q)
            *(uint4*)&Bs[brow[q] * PSTRIDE + buq[q]] = pb[q];
        __syncthreads();

        if (kt + 1 < KT) {
            int ao = (kt + 1) * 4;     // uint4 per row per k-tile (32 fp16 = 64B)
            int bo = (kt + 1) * 16;    // uint2 per row per k-tile
#pragma unroll
            for (int q = 0; q < 2; ++q)
                pa[q] = A4[(size_t)(bm + arow[q]) * K8 + ao + aq[q]];
#pragma unroll
            for (int q = 0; q < 4; ++q)
                pb[q] = *(const uint4*)(B + (size_t)(bn + brow[q]) * Kp + bo + buq[q]);
        }

#pragma unroll
        for (int kh = 0; kh < 2; ++kh) {       // two k16 halves; bytes kh*32
            uint32_t Af[4][4];
#pragma unroll
            for (int mf = 0; mf < 4; ++mf) {
                int rb = wm + mf * 16 + g;
                const uint8_t* base = AsB + rb * ASTRIDE + kh * 32 + t * 4;
                Af[mf][0] = *(const uint32_t*)(base);
                Af[mf][1] = *(const uint32_t*)(base + 8 * ASTRIDE);
                Af[mf][2] = *(const uint32_t*)(base + 16);
                Af[mf][3] = *(const uint32_t*)(base + 8 * ASTRIDE + 16);
            }
            uint2 Bf[4][2];
            int kp = kh * 8;
#pragma unroll
            for (int nf = 0; nf < 4; ++nf) {
                int cb = wn + nf * 8 + g;
                Bf[nf][0] = Bs[cb * PSTRIDE + kp + t];
                Bf[nf][1] = Bs[cb * PSTRIDE + kp + t + 4];
            }
            // term: A . B_hi (16 independent)
#pragma unroll
            for (int nf = 0; nf < 4; ++nf)
#pragma unroll
                for (int mf = 0; mf < 4; ++mf)
                    mma_hf(acc[mf][nf], Af[mf][0], Af[mf][1], Af[mf][2], Af[mf][3],
                           Bf[nf][0].x, Bf[nf][1].x);
            // term: A . B_lo
#pragma unroll
            for (int nf = 0; nf < 4; ++nf)
#pragma unroll
                for (int mf = 0; mf < 4; ++mf)
                    mma_hf(acc[mf][nf], Af[mf][0], Af[mf][1], Af[mf][2], Af[mf][3],
                           Bf[nf][0].y, Bf[nf][1].y);
        }
    }

    // ---- epilogue ----
    float s_main = (OKIND == 1) ? g_inv_sigma[1] : g_inv_sigma[2];
    float s_in = (OKIND == 1) ? g_inv_sigma[0] : 0.0f;
#pragma unroll
    for (int mf = 0; mf < 4; ++mf) {
        int r0 = bm + wm + mf * 16 + g;
#pragma unroll
        for (int nf = 0; nf < 4; ++nf) {
            int c0 = bn + wn + nf * 8 + 2 * t;
            float* a = acc[mf][nf];
#pragma unroll
            for (int half = 0; half < 2; ++half) {
                int rr = r0 + half * 8;
                float v0 = a[half * 2 + 0];
                float v1 = a[half * 2 + 1];
                if (OKIND == 1) {
                    size_t base = (size_t)rr * N + c0;
                    float2 rw = *(const float2*)(raw + base);
                    v0 = tanhf(v0 * s_main + bias[c0] + rw.x * s_in + bias2[c0]);
                    v1 = tanhf(v1 * s_main + bias[c0 + 1] + rw.y * s_in + bias2[c0 + 1]);
                    Cp[base >> 1] = pack_hf(v0, v1);
                } else {
                    size_t base = (size_t)rr * Nreal;
                    if (c0 < Nreal)     Cf[base + c0]     = v0 * s_main + bias[c0];
                    if (c0 + 1 < Nreal) Cf[base + c0 + 1] = v1 * s_main + bias[c0 + 1];
                }
            }
        }
    }
}

// Step 1 (h0 = 0): h = fp16( tanh(raw*s_in + b_in + b_rec) )
__global__ void step1_kernel(const float* __restrict__ xpraw, const float* __restrict__ bin,
                             const float* __restrict__ brec, uint32_t* __restrict__ hp) {
    size_t i = ((size_t)blockIdx.x * blockDim.x + threadIdx.x) * 4;
    float s_in = g_inv_sigma[0];
    float4 v = *(const float4*)(xpraw + i);
    int col = (int)(i & (HID - 1));
    v.x = tanhf(v.x * s_in + bin[col + 0] + brec[col + 0]);
    v.y = tanhf(v.y * s_in + bin[col + 1] + brec[col + 1]);
    v.z = tanhf(v.z * s_in + bin[col + 2] + brec[col + 2]);
    v.w = tanhf(v.w * s_in + bin[col + 3] + brec[col + 3]);
    uint2 o;
    o.x = pack_hf(v.x, v.y);
    o.y = pack_hf(v.z, v.w);
    *(uint2*)(hp + (i >> 1)) = o;
}

// ---------------------------------------------------------------------------
// Launch
// ---------------------------------------------------------------------------
extern "C" void kernel_launch(void* const* d_in, const int* in_sizes, int n_in,
                              void* d_out, int out_size) {
    (void)in_sizes; (void)n_in; (void)out_size;
    const float* x    = (const float*)d_in[0];
    const float* Win  = (const float*)d_in[1];
    const float* bin  = (const float*)d_in[2];
    const float* Wrec = (const float*)d_in[3];
    const float* brec = (const float*)d_in[4];
    const float* Wout = (const float*)d_in[5];
    const float* bout = (const float*)d_in[6];
    float* out = (float*)d_out;

    uint2 *xp, *winp, *wrecp, *woutp;
    uint32_t *hf0, *hf1;
    float* xraw;
    cudaGetSymbolAddress((void**)&xp, g_xp);
    cudaGetSymbolAddress((void**)&winp, g_Winp);
    cudaGetSymbolAddress((void**)&wrecp, g_Wrecp);
    cudaGetSymbolAddress((void**)&woutp, g_Woutp);
    cudaGetSymbolAddress((void**)&xraw, g_xraw);
    cudaGetSymbolAddress((void**)&hf0, g_hf0);
    cudaGetSymbolAddress((void**)&hf1, g_hf1);

    pi_init<<<1, 256>>>();
    prepack_bf<<<(BATCH * IN_DIM / 4) / 256, 256>>>(x, xp, BATCH * IN_DIM / 4);
    prepack_bf<<<(HID * IN_DIM / 4) / 256, 256>>>(Win, winp, HID * IN_DIM / 4);
    prepack_hf<<<(HID * HID / 4) / 256, 256>>>(Wrec, wrecp, HID * HID / 4);
    prepack_hf_pad<<<(NPAD_OUT * HID / 4) / 256, 256>>>(Wout, woutp, OUT_DIM, HID / 4,
                                                        NPAD_OUT * HID / 4);
    // raw xproj GEMM (3-term bf16, sigma-independent)
    gemm_bf3<<<dim3(HID / BN, BATCH / BM), 256>>>(xp, winp, xraw, HID, IN_DIM);

    // --- spectral norms (power iteration, fp32, exact reference sequence) ---
    for (int it = 0; it < NPI; ++it) {
        pi_phaseY<<<NBY, 256>>>(Win, Wrec, Wout);
        pi_phaseZ<<<NBZ, 256>>>(Win, Wrec, Wout);
    }
    pi_phaseY<<<NBY, 256>>>(Win, Wrec, Wout);
    pi_sigma<<<NBZ, 256>>>(Win, Wrec, Wout);
    pi_finalize<<<1, 32>>>();

    // step 1
    step1_kernel<<<(BATCH * HID) / (256 * 4), 256>>>(xraw, bin, brec, hf0);

    // steps 2..30 (2-term fp16)
    uint32_t* hin = hf0;
    uint32_t* hout = hf1;
    for (int s = 1; s < STEPS; ++s) {
        gemm_h2<1><<<dim3(HID / BN, BATCH / BM), 256>>>(
            hin, wrecp, brec, bin, xraw, nullptr, hout, HID, HID, HID);
        uint32_t* tmp = hin; hin = hout; hout = tmp;
    }

    // out GEMM (2-term fp16, B padded to 1024 rows; stores col-guarded)
    gemm_h2<2><<<dim3(NPAD_OUT / BN, BATCH / BM), 256>>>(
        hin, woutp, bout, nullptr, nullptr, out, nullptr, NPAD_OUT, OUT_DIM, HID);
}

// round 13
// speedup vs baseline: 2.5536x; 1.1154x over previous
#include <cuda_runtime.h>
#include <cuda_fp16.h>
#include <cstdint>

// ---------------------------------------------------------------------------
// Problem constants
// ---------------------------------------------------------------------------
#define IN_DIM   1024
#define HID      2048
#define OUT_DIM  1000
#define NPAD_OUT 1024
#define BATCH    4096
#define STEPS    30
#define NPI      30
#define EPSN     1e-12f

#define GZ_IN  128
#define GZ_REC 256
#define GZ_OUT 64
#define NBZ (GZ_IN + GZ_REC + GZ_OUT)   // 448
#define GY_IN  32
#define GY_REC 64
#define GY_OUT 64
#define NBY (GY_IN + GY_REC + GY_OUT)   // 160

// ---------------------------------------------------------------------------
// Device scratch
// ---------------------------------------------------------------------------
__device__ float g_u[6144];
__device__ float g_y[6144];
__device__ float g_partY[3][64];
__device__ float g_partZ[3][256];
__device__ float g_sigpart[3][256];
__device__ float g_inv_sigma[3];

__device__ uint2 g_xp[(size_t)BATCH * IN_DIM / 2];
__device__ uint2 g_Winp[(size_t)HID * IN_DIM / 2];
__device__ uint2 g_Wrecp[(size_t)HID * HID / 2];
__device__ uint2 g_Woutp[(size_t)NPAD_OUT * HID / 2];
__device__ float g_xraw[(size_t)BATCH * HID];
__device__ uint32_t g_hf0[(size_t)BATCH * HID / 2];
__device__ uint32_t g_hf1[(size_t)BATCH * HID / 2];

// ---------------------------------------------------------------------------
// helpers
// ---------------------------------------------------------------------------
__device__ __forceinline__ uint32_t smem_u32(const void* p) {
    uint32_t a;
    asm("{ .reg .u64 t; cvta.to.shared.u64 t, %1; cvt.u32.u64 %0, t; }" : "=r"(a) : "l"(p));
    return a;
}
#define CP16(dst, src) \
    asm volatile("cp.async.cg.shared.global [%0], [%1], 16;" :: "r"(dst), "l"(src) : "memory")
#define CP_COMMIT() asm volatile("cp.async.commit_group;" ::: "memory")
#define CP_WAIT(n) asm volatile("cp.async.wait_group %0;" :: "n"(n) : "memory")

__device__ __forceinline__ void split2_bf(float x0, float x1, uint32_t& hi, uint32_t& lo) {
    uint32_t h;
    asm("cvt.rn.bf16x2.f32 %0, %1, %2;" : "=r"(h) : "f"(x1), "f"(x0));
    float h0 = __uint_as_float(h << 16);
    float h1 = __uint_as_float(h & 0xffff0000u);
    float r0 = x0 - h0, r1 = x1 - h1;
    uint32_t l;
    asm("cvt.rn.bf16x2.f32 %0, %1, %2;" : "=r"(l) : "f"(r1), "f"(r0));
    hi = h; lo = l;
}

__device__ __forceinline__ void split2_hf(float x0, float x1, uint32_t& hi, uint32_t& lo) {
    __half a = __float2half_rn(x0), b = __float2half_rn(x1);
    __half2 hh = __halves2half2(a, b);
    float r0 = x0 - __half2float(a), r1 = x1 - __half2float(b);
    __half2 ll = __halves2half2(__float2half_rn(r0), __float2half_rn(r1));
    hi = *(uint32_t*)&hh; lo = *(uint32_t*)&ll;
}

__device__ __forceinline__ uint32_t pack_hf(float x0, float x1) {
    __half2 hh = __halves2half2(__float2half_rn(x0), __float2half_rn(x1));
    return *(uint32_t*)&hh;
}

// ---------------------------------------------------------------------------
// Prepack kernels
// ---------------------------------------------------------------------------
__global__ void prepack_bf(const float* __restrict__ src, uint2* __restrict__ dst, int n4) {
    int i = blockIdx.x * 256 + threadIdx.x;
    if (i < n4) {
        float4 v = ((const float4*)src)[i];
        uint32_t h01, l01, h23, l23;
        split2_bf(v.x, v.y, h01, l01);
        split2_bf(v.z, v.w, h23, l23);
        ((uint4*)dst)[i] = make_uint4(h01, l01, h23, l23);
    }
}

__global__ void prepack_hf(const float* __restrict__ src, uint2* __restrict__ dst, int n4) {
    int i = blockIdx.x * 256 + threadIdx.x;
    if (i < n4) {
        float4 v = ((const float4*)src)[i];
        uint32_t h01, l01, h23, l23;
        split2_hf(v.x, v.y, h01, l01);
        split2_hf(v.z, v.w, h23, l23);
        ((uint4*)dst)[i] = make_uint4(h01, l01, h23, l23);
    }
}

__global__ void prepack_hf_pad(const float* __restrict__ src, uint2* __restrict__ dst,
                               int src_rows, int K4, int n4) {
    int i = blockIdx.x * 256 + threadIdx.x;
    if (i < n4) {
        int row = i / K4;
        uint4 o = make_uint4(0u, 0u, 0u, 0u);
        if (row < src_rows) {
            float4 v = ((const float4*)src)[i];
            uint32_t h01, l01, h23, l23;
            split2_hf(v.x, v.y, h01, l01);
            split2_hf(v.z, v.w, h23, l23);
            o = make_uint4(h01, l01, h23, l23);
        }
        ((uint4*)dst)[i] = o;
    }
}

// ---------------------------------------------------------------------------
// Power iteration (fp32, reference-exact sequence) — proven multi-launch form
// ---------------------------------------------------------------------------
struct PiCtx { int m, bg, G, M, N; const float* W; float* ubuf; float* ybuf; };

__device__ __forceinline__ PiCtx pi_ctxZ(int b, const float* Win, const float* Wrec,
                                         const float* Wout) {
    PiCtx c;
    if (b < GZ_IN) {
        c.m = 0; c.bg = b; c.G = GZ_IN; c.M = HID; c.N = IN_DIM;
        c.W = Win; c.ubuf = g_u; c.ybuf = g_y;
    } else if (b < GZ_IN + GZ_REC) {
        c.m = 1; c.bg = b - GZ_IN; c.G = GZ_REC; c.M = HID; c.N = HID;
        c.W = Wrec; c.ubuf = g_u + 2048; c.ybuf = g_y + 2048;
    } else {
        c.m = 2; c.bg = b - GZ_IN - GZ_REC; c.G = GZ_OUT; c.M = OUT_DIM; c.N = HID;
        c.W = Wout; c.ubuf = g_u + 4096; c.ybuf = g_y + 4096;
    }
    return c;
}

__device__ __forceinline__ PiCtx pi_ctxY(int b, const float* Win, const float* Wrec,
                                         const float* Wout) {
    PiCtx c;
    if (b < GY_IN) {
        c.m = 0; c.bg = b; c.G = GY_IN; c.M = HID; c.N = IN_DIM;
        c.W = Win; c.ubuf = g_u; c.ybuf = g_y;
    } else if (b < GY_IN + GY_REC) {
        c.m = 1; c.bg = b - GY_IN; c.G = GY_REC; c.M = HID; c.N = HID;
        c.W = Wrec; c.ubuf = g_u + 2048; c.ybuf = g_y + 2048;
    } else {
        c.m = 2; c.bg = b - GY_IN - GY_REC; c.G = GY_OUT; c.M = OUT_DIM; c.N = HID;
        c.W = Wout; c.ubuf = g_u + 4096; c.ybuf = g_y + 4096;
    }
    return c;
}

__device__ __forceinline__ float block_sum_partials(const float* part, int G, float* red) {
    int t = threadIdx.x;
    red[t] = (t < G) ? part[t] : 0.0f;
    __syncthreads();
#pragma unroll
    for (int s = 128; s > 0; s >>= 1) {
        if (t < s) red[t] += red[t + s];
        __syncthreads();
    }
    float v = red[0];
    __syncthreads();
    return v;
}

__global__ void pi_init() {
    int t = threadIdx.x;
    for (int i = t; i < 2048; i += 256) {
        g_u[i] = 1.0f;
        g_u[2048 + i] = 1.0f;
        if (i < OUT_DIM) g_u[4096 + i] = 1.0f;
    }
    for (int g = t; g < 256; g += 256) {
        g_partZ[0][g] = 0.0f; g_partZ[1][g] = 0.0f; g_partZ[2][g] = 0.0f;
    }
    if (t == 0) {
        g_partZ[0][0] = (float)HID;
        g_partZ[1][0] = (float)HID;
        g_partZ[2][0] = (float)OUT_DIM;
    }
}

__global__ void pi_phaseY(const float* __restrict__ Win, const float* __restrict__ Wrec,
                          const float* __restrict__ Wout) {
    PiCtx c = pi_ctxY(blockIdx.x, Win, Wrec, Wout);
    int gz = (c.m == 1) ? GZ_REC : ((c.m == 0) ? GZ_IN : GZ_OUT);
    __shared__ float red[256];
    __shared__ float ssq[32];
    float ss = block_sum_partials(g_partZ[c.m], gz, red);
    float su = 1.0f / (sqrtf(ss) + EPSN);

    int cl = threadIdx.x & 31;
    int seg = threadIdx.x >> 5;
    int col = c.bg * 32 + cl;
    int rps = (c.M + 7) / 8;
    int r0 = seg * rps;
    int iend = min(r0 + rps, c.M);

    const float* Wc = c.W + col;
    float a0=0.f,a1=0.f,a2=0.f,a3=0.f,a4=0.f,a5=0.f,a6=0.f,a7=0.f;
    int i = r0;
    for (; i + 7 < iend; i += 8) {
        a0 += Wc[(size_t)(i+0)*c.N] * c.ubuf[i+0];
        a1 += Wc[(size_t)(i+1)*c.N] * c.ubuf[i+1];
        a2 += Wc[(size_t)(i+2)*c.N] * c.ubuf[i+2];
        a3 += Wc[(size_t)(i+3)*c.N] * c.ubuf[i+3];
        a4 += Wc[(size_t)(i+4)*c.N] * c.ubuf[i+4];
        a5 += Wc[(size_t)(i+5)*c.N] * c.ubuf[i+5];
        a6 += Wc[(size_t)(i+6)*c.N] * c.ubuf[i+6];
        a7 += Wc[(size_t)(i+7)*c.N] * c.ubuf[i+7];
    }
    for (; i < iend; ++i) a0 += Wc[(size_t)i*c.N] * c.ubuf[i];
    float acc = ((a0+a1)+(a2+a3)) + ((a4+a5)+(a6+a7));

    red[threadIdx.x] = acc;
    __syncthreads();
    if (seg == 0) {
        float tot = 0.0f;
        for (int s = 0; s < 8; ++s) tot += red[cl + s * 32];
        float yv = tot * su;
        c.ybuf[col] = yv;
        ssq[cl] = yv * yv;
    }
    __syncthreads();
    if (threadIdx.x == 0) {
        float p = 0.0f;
        for (int q = 0; q < 32; ++q) p += ssq[q];
        g_partY[c.m][c.bg] = p;
    }
}

__global__ void pi_phaseZ(const float* __restrict__ Win, const float* __restrict__ Wrec,
                          const float* __restrict__ Wout) {
    PiCtx c = pi_ctxZ(blockIdx.x, Win, Wrec, Wout);
    int gy = (c.m == 1) ? GY_REC : ((c.m == 0) ? GY_IN : GY_OUT);
    __shared__ float red[256];
    float ss = block_sum_partials(g_partY[c.m], gy, red);
    float sv = 1.0f / (sqrtf(ss) + EPSN);

    int warp = threadIdx.x >> 5, lane = threadIdx.x & 31;
    int rpb = (c.M + c.G - 1) / c.G;
    int rend = min(c.bg * rpb + rpb, c.M);

    float acc2 = 0.0f;
    for (int r = c.bg * rpb + warp; r < rend; r += 8) {
        const float* row = c.W + (size_t)r * c.N;
        float a0=0.f,a1=0.f,a2=0.f,a3=0.f,a4=0.f,a5=0.f,a6=0.f,a7=0.f;
        for (int j = lane; j < c.N; j += 256) {
            a0 += row[j      ] * c.ybuf[j      ];
            a1 += row[j +  32] * c.ybuf[j +  32];
            a2 += row[j +  64] * c.ybuf[j +  64];
            a3 += row[j +  96] * c.ybuf[j +  96];
            a4 += row[j + 128] * c.ybuf[j + 128];
            a5 += row[j + 160] * c.ybuf[j + 160];
            a6 += row[j + 192] * c.ybuf[j + 192];
            a7 += row[j + 224] * c.ybuf[j + 224];
        }
        float a = ((a0+a1)+(a2+a3)) + ((a4+a5)+(a6+a7));
        for (int o = 16; o; o >>= 1) a += __shfl_down_sync(0xffffffffu, a, o);
        if (lane == 0) {
            float z = a * sv;
            c.ubuf[r] = z;
            acc2 += z * z;
        }
    }
    __shared__ float wsq[8];
    if (lane == 0) wsq[warp] = acc2;
    __syncthreads();
    if (threadIdx.x == 0) {
        float p = 0.0f;
        for (int w = 0; w < 8; ++w) p += wsq[w];
        g_partZ[c.m][c.bg] = p;
    }
}

__global__ void pi_sigma(const float* __restrict__ Win, const float* __restrict__ Wrec,
                         const float* __restrict__ Wout) {
    PiCtx c = pi_ctxZ(blockIdx.x, Win, Wrec, Wout);
    int gy = (c.m == 1) ? GY_REC : ((c.m == 0) ? GY_IN : GY_OUT);
    __shared__ float red[256];
    float ssz = block_sum_partials(g_partZ[c.m], c.G, red);
    float ssy = block_sum_partials(g_partY[c.m], gy, red);
    float su = 1.0f / (sqrtf(ssz) + EPSN);
    float sv = 1.0f / (sqrtf(ssy) + EPSN);

    int warp = threadIdx.x >> 5, lane = threadIdx.x & 31;
    int rpb = (c.M + c.G - 1) / c.G;
    int rend = min(c.bg * rpb + rpb, c.M);

    float contrib = 0.0f;
    for (int r = c.bg * rpb + warp; r < rend; r += 8) {
        const float* row = c.W + (size_t)r * c.N;
        float a0=0.f,a1=0.f,a2=0.f,a3=0.f,a4=0.f,a5=0.f,a6=0.f,a7=0.f;
        for (int j = lane; j < c.N; j += 256) {
            a0 += row[j      ] * c.ybuf[j      ];
            a1 += row[j +  32] * c.ybuf[j +  32];
            a2 += row[j +  64] * c.ybuf[j +  64];
            a3 += row[j +  96] * c.ybuf[j +  96];
            a4 += row[j + 128] * c.ybuf[j + 128];
            a5 += row[j + 160] * c.ybuf[j + 160];
            a6 += row[j + 192] * c.ybuf[j + 192];
            a7 += row[j + 224] * c.ybuf[j + 224];
        }
        float a = ((a0+a1)+(a2+a3)) + ((a4+a5)+(a6+a7));
        for (int o = 16; o; o >>= 1) a += __shfl_down_sync(0xffffffffu, a, o);
        if (lane == 0) contrib += (su * c.ubuf[r]) * (sv * a);
    }
    __shared__ float wsq[8];
    if (lane == 0) wsq[warp] = contrib;
    __syncthreads();
    if (threadIdx.x == 0) {
        float p = 0.0f;
        for (int w = 0; w < 8; ++w) p += wsq[w];
        g_sigpart[c.m][c.bg] = p;
    }
}

__global__ void pi_finalize() {
    int m = threadIdx.x;
    if (m < 3) {
        int G = (m == 1) ? GZ_REC : ((m == 0) ? GZ_IN : GZ_OUT);
        float s = 0.0f;
        for (int g = 0; g < G; ++g) s += g_sigpart[m][g];
        g_inv_sigma[m] = 1.0f / s;
    }
}

// ---------------------------------------------------------------------------
// MMA wrappers
// ---------------------------------------------------------------------------
__device__ __forceinline__ void mma_bf(float* c, uint32_t a0, uint32_t a1, uint32_t a2,
                                       uint32_t a3, uint32_t b0, uint32_t b1) {
    asm volatile(
        "mma.sync.aligned.m16n8k16.row.col.f32.bf16.bf16.f32 "
        "{%0,%1,%2,%3}, {%4,%5,%6,%7}, {%8,%9}, {%0,%1,%2,%3};"
        : "+f"(c[0]), "+f"(c[1]), "+f"(c[2]), "+f"(c[3])
        : "r"(a0), "r"(a1), "r"(a2), "r"(a3), "r"(b0), "r"(b1));
}
__device__ __forceinline__ void mma_hf(float* c, uint32_t a0, uint32_t a1, uint32_t a2,
                                       uint32_t a3, uint32_t b0, uint32_t b1) {
    asm volatile(
        "mma.sync.aligned.m16n8k16.row.col.f32.f16.f16.f32 "
        "{%0,%1,%2,%3}, {%4,%5,%6,%7}, {%8,%9}, {%0,%1,%2,%3};"
        : "+f"(c[0]), "+f"(c[1]), "+f"(c[2]), "+f"(c[3])
        : "r"(a0), "r"(a1), "r"(a2), "r"(a3), "r"(b0), "r"(b1));
}

#define BM 128
#define BN 128
#define BKT 32
#define PSTRIDE 20     // uint2 per packed-pair row (160B)
#define ASTRIDE 80     // bytes per fp16 A row (64 data + 16 pad)
#define A_ST_BYTES 10240
#define B_ST_BYTES 20480
#define H2_SMEM (2 * A_ST_BYTES + 2 * B_ST_BYTES)   // 61440

// ---------------------------------------------------------------------------
// 3-term bf16 GEMM on packed pairs (xproj only)
// ---------------------------------------------------------------------------
__global__ __launch_bounds__(256)
void gemm_bf3(const uint2* __restrict__ A, const uint2* __restrict__ B,
              float* __restrict__ Cf, int N, int K) {
    __shared__ __align__(16) uint2 As[BM * PSTRIDE];
    __shared__ __align__(16) uint2 Bs[BN * PSTRIDE];

    int tid = threadIdx.x;
    int bm = blockIdx.y * BM, bn = blockIdx.x * BN;
    int Kp = K >> 1;

    int rowq[4], uq[4];
#pragma unroll
    for (int q = 0; q < 4; ++q) {
        int idx = tid + q * 256;
        rowq[q] = idx >> 3;
        uq[q] = (idx & 7) * 2;
    }

    int warp = tid >> 5, lane = tid & 31;
    int wm = (warp & 1) * 64;
    int wn = (warp >> 1) * 32;
    int g = lane >> 2;
    int t = lane & 3;

    float acc[4][4][4];
#pragma unroll
    for (int i = 0; i < 4; ++i)
#pragma unroll
        for (int j = 0; j < 4; ++j)
#pragma unroll
            for (int q = 0; q < 4; ++q) acc[i][j][q] = 0.0f;

    uint4 pa[4], pb[4];
#pragma unroll
    for (int q = 0; q < 4; ++q) {
        pa[q] = *(const uint4*)(A + (size_t)(bm + rowq[q]) * Kp + uq[q]);
        pb[q] = *(const uint4*)(B + (size_t)(bn + rowq[q]) * Kp + uq[q]);
    }

    int KT = K / BKT;
    for (int kt = 0; kt < KT; ++kt) {
        __syncthreads();
#pragma unroll
        for (int q = 0; q < 4; ++q) {
            *(uint4*)&As[rowq[q] * PSTRIDE + uq[q]] = pa[q];
            *(uint4*)&Bs[rowq[q] * PSTRIDE + uq[q]] = pb[q];
        }
        __syncthreads();

        if (kt + 1 < KT) {
            int off = (kt + 1) * 16;
#pragma unroll
            for (int q = 0; q < 4; ++q) {
                pa[q] = *(const uint4*)(A + (size_t)(bm + rowq[q]) * Kp + off + uq[q]);
                pb[q] = *(const uint4*)(B + (size_t)(bn + rowq[q]) * Kp + off + uq[q]);
            }
        }

#pragma unroll
        for (int kp = 0; kp < 16; kp += 8) {
            uint2 Af[4][4];
            uint2 Bf[4][2];
#pragma unroll
            for (int mf = 0; mf < 4; ++mf) {
                int rb = wm + mf * 16 + g;
                Af[mf][0] = As[rb * PSTRIDE + kp + t];
                Af[mf][1] = As[(rb + 8) * PSTRIDE + kp + t];
                Af[mf][2] = As[rb * PSTRIDE + kp + t + 4];
                Af[mf][3] = As[(rb + 8) * PSTRIDE + kp + t + 4];
            }
#pragma unroll
            for (int nf = 0; nf < 4; ++nf) {
                int cb = wn + nf * 8 + g;
                Bf[nf][0] = Bs[cb * PSTRIDE + kp + t];
                Bf[nf][1] = Bs[cb * PSTRIDE + kp + t + 4];
            }
#pragma unroll
            for (int nf = 0; nf < 4; ++nf)
#pragma unroll
                for (int mf = 0; mf < 4; ++mf)
                    mma_bf(acc[mf][nf], Af[mf][0].x, Af[mf][1].x, Af[mf][2].x, Af[mf][3].x,
                           Bf[nf][0].x, Bf[nf][1].x);
#pragma unroll
            for (int nf = 0; nf < 4; ++nf)
#pragma unroll
                for (int mf = 0; mf < 4; ++mf)
                    mma_bf(acc[mf][nf], Af[mf][0].x, Af[mf][1].x, Af[mf][2].x, Af[mf][3].x,
                           Bf[nf][0].y, Bf[nf][1].y);
#pragma unroll
            for (int nf = 0; nf < 4; ++nf)
#pragma unroll
                for (int mf = 0; mf < 4; ++mf)
                    mma_bf(acc[mf][nf], Af[mf][0].y, Af[mf][1].y, Af[mf][2].y, Af[mf][3].y,
                           Bf[nf][0].x, Bf[nf][1].x);
        }
    }

#pragma unroll
    for (int mf = 0; mf < 4; ++mf) {
        int r0 = bm + wm + mf * 16 + g;
#pragma unroll
        for (int nf = 0; nf < 4; ++nf) {
            int c0 = bn + wn + nf * 8 + 2 * t;
            float* a = acc[mf][nf];
#pragma unroll
            for (int half = 0; half < 2; ++half) {
                int rr = r0 + half * 8;
                float2 o; o.x = a[half * 2 + 0]; o.y = a[half * 2 + 1];
                *(float2*)(Cf + (size_t)rr * N + c0) = o;
            }
        }
    }
}

// ---------------------------------------------------------------------------
// 2-term fp16 GEMM with cp.async 2-stage pipeline, 2 CTAs/SM.
// ---------------------------------------------------------------------------
template <int OKIND>
__global__ __launch_bounds__(256, 2)
void gemm_h2(const uint32_t* __restrict__ Ah, const uint2* __restrict__ B,
             const float* __restrict__ bias, const float* __restrict__ bias2,
             const float* __restrict__ raw, float* __restrict__ Cf,
             uint32_t* __restrict__ Cp, int N, int Nreal, int K) {
    extern __shared__ __align__(16) uint8_t dynsmem[];
    uint32_t sbase = smem_u32(dynsmem);
    const uint32_t aoff[2] = { 0u, A_ST_BYTES };
    const uint32_t boff[2] = { 2u * A_ST_BYTES, 2u * A_ST_BYTES + B_ST_BYTES };

    int tid = threadIdx.x;
    int bm = blockIdx.y * BM, bn = blockIdx.x * BN;
    int K8 = K >> 3;
    int Kp = K >> 1;

    int arow[2], aq[2];
#pragma unroll
    for (int q = 0; q < 2; ++q) {
        int idx = tid + q * 256;
        arow[q] = idx >> 2;
        aq[q] = idx & 3;
    }
    int brow[4], buq[4];
#pragma unroll
    for (int q = 0; q < 4; ++q) {
        int idx = tid + q * 256;
        brow[q] = idx >> 3;
        buq[q] = (idx & 7) * 2;
    }

    const uint4* A4 = (const uint4*)Ah;

    auto issue_tile = [&](int kt, int s) {
#pragma unroll
        for (int q = 0; q < 2; ++q)
            CP16(sbase + aoff[s] + arow[q] * ASTRIDE + aq[q] * 16,
                 A4 + (size_t)(bm + arow[q]) * K8 + kt * 4 + aq[q]);
#pragma unroll
        for (int q = 0; q < 4; ++q)
            CP16(sbase + boff[s] + brow[q] * 160 + buq[q] * 8,
                 (const uint4*)(B + (size_t)(bn + brow[q]) * Kp + kt * 16 + buq[q]));
        CP_COMMIT();
    };

    int warp = tid >> 5, lane = tid & 31;
    int wm = (warp & 1) * 64;
    int wn = (warp >> 1) * 32;
    int g = lane >> 2;
    int t = lane & 3;

    float acc[4][4][4];
#pragma unroll
    for (int i = 0; i < 4; ++i)
#pragma unroll
        for (int j = 0; j < 4; ++j)
#pragma unroll
            for (int q = 0; q < 4; ++q) acc[i][j][q] = 0.0f;

    int KT = K / BKT;
    issue_tile(0, 0);
    issue_tile(1, 1);

    for (int kt = 0; kt < KT; ++kt) {
        int s = kt & 1;
        if (kt + 1 < KT) { CP_WAIT(1); } else { CP_WAIT(0); }
        __syncthreads();

        const uint8_t* AsB = dynsmem + aoff[s];
        const uint2* Bs = (const uint2*)(dynsmem + boff[s]);
#pragma unroll
        for (int kh = 0; kh < 2; ++kh) {
            uint32_t Af[4][4];
#pragma unroll
            for (int mf = 0; mf < 4; ++mf) {
                int rb = wm + mf * 16 + g;
                const uint8_t* base = AsB + rb * ASTRIDE + kh * 32 + t * 4;
                Af[mf][0] = *(const uint32_t*)(base);
                Af[mf][1] = *(const uint32_t*)(base + 8 * ASTRIDE);
                Af[mf][2] = *(const uint32_t*)(base + 16);
                Af[mf][3] = *(const uint32_t*)(base + 8 * ASTRIDE + 16);
            }
            uint2 Bf[4][2];
            int kp = kh * 8;
#pragma unroll
            for (int nf = 0; nf < 4; ++nf) {
                int cb = wn + nf * 8 + g;
                Bf[nf][0] = Bs[cb * PSTRIDE + kp + t];
                Bf[nf][1] = Bs[cb * PSTRIDE + kp + t + 4];
            }
#pragma unroll
            for (int nf = 0; nf < 4; ++nf)
#pragma unroll
                for (int mf = 0; mf < 4; ++mf)
                    mma_hf(acc[mf][nf], Af[mf][0], Af[mf][1], Af[mf][2], Af[mf][3],
                           Bf[nf][0].x, Bf[nf][1].x);
#pragma unroll
            for (int nf = 0; nf < 4; ++nf)
#pragma unroll
                for (int mf = 0; mf < 4; ++mf)
                    mma_hf(acc[mf][nf], Af[mf][0], Af[mf][1], Af[mf][2], Af[mf][3],
                           Bf[nf][0].y, Bf[nf][1].y);
        }
        __syncthreads();
        if (kt + 2 < KT) issue_tile(kt + 2, s);
    }

    // ---- epilogue ----
    float s_main = (OKIND == 1) ? g_inv_sigma[1] : g_inv_sigma[2];
    float s_in = (OKIND == 1) ? g_inv_sigma[0] : 0.0f;
#pragma unroll
    for (int mf = 0; mf < 4; ++mf) {
        int r0 = bm + wm + mf * 16 + g;
#pragma unroll
        for (int nf = 0; nf < 4; ++nf) {
            int c0 = bn + wn + nf * 8 + 2 * t;
            float* a = acc[mf][nf];
#pragma unroll
            for (int half = 0; half < 2; ++half) {
                int rr = r0 + half * 8;
                float v0 = a[half * 2 + 0];
                float v1 = a[half * 2 + 1];
                if (OKIND == 1) {
                    size_t base = (size_t)rr * N + c0;
                    float2 rw = *(const float2*)(raw + base);
                    v0 = tanhf(v0 * s_main + bias[c0] + rw.x * s_in + bias2[c0]);
                    v1 = tanhf(v1 * s_main + bias[c0 + 1] + rw.y * s_in + bias2[c0 + 1]);
                    Cp[base >> 1] = pack_hf(v0, v1);
                } else {
                    size_t base = (size_t)rr * Nreal;
                    if (c0 < Nreal)     Cf[base + c0]     = v0 * s_main + bias[c0];
                    if (c0 + 1 < Nreal) Cf[base + c0 + 1] = v1 * s_main + bias[c0 + 1];
                }
            }
        }
    }
}

// Step 1 (h0 = 0): h = fp16( tanh(raw*s_in + b_in + b_rec) )
__global__ void step1_kernel(const float* __restrict__ xpraw, const float* __restrict__ bin,
                             const float* __restrict__ brec, uint32_t* __restrict__ hp) {
    size_t i = ((size_t)blockIdx.x * blockDim.x + threadIdx.x) * 4;
    float s_in = g_inv_sigma[0];
    float4 v = *(const float4*)(xpraw + i);
    int col = (int)(i & (HID - 1));
    v.x = tanhf(v.x * s_in + bin[col + 0] + brec[col + 0]);
    v.y = tanhf(v.y * s_in + bin[col + 1] + brec[col + 1]);
    v.z = tanhf(v.z * s_in + bin[col + 2] + brec[col + 2]);
    v.w = tanhf(v.w * s_in + bin[col + 3] + brec[col + 3]);
    uint2 o;
    o.x = pack_hf(v.x, v.y);
    o.y = pack_hf(v.z, v.w);
    *(uint2*)(hp + (i >> 1)) = o;
}

// ---------------------------------------------------------------------------
// Launch
// ---------------------------------------------------------------------------
extern "C" void kernel_launch(void* const* d_in, const int* in_sizes, int n_in,
                              void* d_out, int out_size) {
    (void)in_sizes; (void)n_in; (void)out_size;
    const float* x    = (const float*)d_in[0];
    const float* Win  = (const float*)d_in[1];
    const float* bin  = (const float*)d_in[2];
    const float* Wrec = (const float*)d_in[3];
    const float* brec = (const float*)d_in[4];
    const float* Wout = (const float*)d_in[5];
    const float* bout = (const float*)d_in[6];
    float* out = (float*)d_out;

    uint2 *xp, *winp, *wrecp, *woutp;
    uint32_t *hf0, *hf1;
    float* xraw;
    cudaGetSymbolAddress((void**)&xp, g_xp);
    cudaGetSymbolAddress((void**)&winp, g_Winp);
    cudaGetSymbolAddress((void**)&wrecp, g_Wrecp);
    cudaGetSymbolAddress((void**)&woutp, g_Woutp);
    cudaGetSymbolAddress((void**)&xraw, g_xraw);
    cudaGetSymbolAddress((void**)&hf0, g_hf0);
    cudaGetSymbolAddress((void**)&hf1, g_hf1);

    cudaFuncSetAttribute(gemm_h2<1>, cudaFuncAttributeMaxDynamicSharedMemorySize, H2_SMEM);
    cudaFuncSetAttribute(gemm_h2<2>, cudaFuncAttributeMaxDynamicSharedMemorySize, H2_SMEM);

    pi_init<<<1, 256>>>();
    prepack_bf<<<(BATCH * IN_DIM / 4) / 256, 256>>>(x, xp, BATCH * IN_DIM / 4);
    prepack_bf<<<(HID * IN_DIM / 4) / 256, 256>>>(Win, winp, HID * IN_DIM / 4);
    prepack_hf<<<(HID * HID / 4) / 256, 256>>>(Wrec, wrecp, HID * HID / 4);
    prepack_hf_pad<<<(NPAD_OUT * HID / 4) / 256, 256>>>(Wout, woutp, OUT_DIM, HID / 4,
                                                        NPAD_OUT * HID / 4);
    // raw xproj GEMM (3-term bf16, sigma-independent)
    gemm_bf3<<<dim3(HID / BN, BATCH / BM), 256>>>(xp, winp, xraw, HID, IN_DIM);

    // --- spectral norms: proven multi-launch power iteration ---
    for (int it = 0; it < NPI; ++it) {
        pi_phaseY<<<NBY, 256>>>(Win, Wrec, Wout);
        pi_phaseZ<<<NBZ, 256>>>(Win, Wrec, Wout);
    }
    pi_phaseY<<<NBY, 256>>>(Win, Wrec, Wout);
    pi_sigma<<<NBZ, 256>>>(Win, Wrec, Wout);
    pi_finalize<<<1, 32>>>();

    // step 1
    step1_kernel<<<(BATCH * HID) / (256 * 4), 256>>>(xraw, bin, brec, hf0);

    // steps 2..30 (2-term fp16, cp.async pipeline)
    uint32_t* hin = hf0;
    uint32_t* hout = hf1;
    for (int s = 1; s < STEPS; ++s) {
        gemm_h2<1><<<dim3(HID / BN, BATCH / BM), 256, H2_SMEM>>>(
            hin, wrecp, brec, bin, xraw, nullptr, hout, HID, HID, HID);
        uint32_t* tmp = hin; hin = hout; hout = tmp;
    }

    // out GEMM
    gemm_h2<2><<<dim3(NPAD_OUT / BN, BATCH / BM), 256, H2_SMEM>>>(
        hin, woutp, bout, nullptr, nullptr, out, nullptr, NPAD_OUT, OUT_DIM, HID);
}